// round 1
// baseline (speedup 1.0000x reference)
#include <cuda_runtime.h>
#include <cuda_bf16.h>

// ---------------------------------------------------------------------------
// AttentionCritic: N=4 agents, B=32768, S=512, A=64, H=256, NH=16, D=16
// Pipeline (all fp32 this round):
//   1. batch stats for states/actions (BN folds into encoder weights)
//   2. fold weights: Wcomb [576 x 512] (cols 0..255 sa_enc, 256..511 s_enc)
//   3. GEMM enc: [states|actions] @ Wcomb -> ENC (lrelu+bias)
//   4. GEMM kv:  sa_enc @ Wkv -> keys(0..255) | vals(256..511, bias+lrelu)
//      GEMM sel: s_enc @ Wsel -> sel(512..767)            (into KVS, ldc=768)
//   5. attention: per (b, head): 4x4 softmax over agents, writes `other`
//      into ENC cols 0..255 (overwriting dead sa_enc)
//   6. GEMM fc1: ENC @ Wc1p (rows pre-swapped) -> H (bias+lrelu)
//   7. fc2+gather: q = H . Wc2[:, argmax(actions)] + bc2[idx]
// GEMMs use packed fma.rn.f32x2 (FFMA2) for 2x fp32 throughput.
// ---------------------------------------------------------------------------

#define NAG   4
#define BATCH 32768
#define ROWS  (NAG * BATCH)       // 131072
#define SDIM  512
#define ADIM  64
#define SADIM 576
#define HDIM  256
#define NHEAD 16
#define DHEAD 16

// ---- scratch layout (floats) ----
constexpr size_t O_SUM   = 0;             // 2304 (4*576)
constexpr size_t O_SSQ   = 2304;          // 2304
constexpr size_t O_MEAN  = 4608;          // 2304
constexpr size_t O_ISTD  = 6912;          // 2304
constexpr size_t O_BCOMB = 9216;          // 2048 (4*512)
constexpr size_t O_WCOMB = 11264;         // 4*576*512 = 1179648
constexpr size_t O_WKV   = 1190912;       // 256*512   = 131072
constexpr size_t O_WSEL  = 1321984;       // 256*256   = 65536
constexpr size_t O_WC1P  = 1387520;       // 4*512*256 = 524288
constexpr size_t O_ENC   = 1911808;       // 131072*512 = 67108864
constexpr size_t O_KVS   = 69020672;      // 131072*768 = 100663296
constexpr size_t O_H     = 169683968;     // 131072*256 = 33554432
constexpr size_t SCRATCH_FLOATS = 203238400;

__device__ float g_scratch[SCRATCH_FLOATS];

// ---- packed f32x2 helpers ----
__device__ __forceinline__ unsigned long long pack2(float lo, float hi) {
    unsigned long long r;
    asm("mov.b64 %0, {%1, %2};" : "=l"(r) : "f"(lo), "f"(hi));
    return r;
}
__device__ __forceinline__ unsigned long long fma2(unsigned long long a,
                                                   unsigned long long b,
                                                   unsigned long long c) {
    unsigned long long d;
    asm("fma.rn.f32x2 %0, %1, %2, %3;" : "=l"(d) : "l"(a), "l"(b), "l"(c));
    return d;
}
__device__ __forceinline__ float2 unpack2(unsigned long long v) {
    float2 f;
    asm("mov.b64 {%0, %1}, %2;" : "=f"(f.x), "=f"(f.y) : "l"(v));
    return f;
}

// ---------------------------------------------------------------------------
__global__ void k_zero(float* p, int n) {
    int i = blockIdx.x * blockDim.x + threadIdx.x;
    if (i < n) p[i] = 0.f;
}

// grid (4, 64), block 576. thread f: feature column (states 0..511, actions 512..575)
__global__ void k_stats(const float* __restrict__ states,
                        const float* __restrict__ actions,
                        float* __restrict__ sum, float* __restrict__ ssq) {
    int n = blockIdx.x, slab = blockIdx.y, f = threadIdx.x;
    const int RPS = BATCH / 64;   // 512 rows per slab
    int b0 = slab * RPS;
    float s = 0.f, s2 = 0.f;
    if (f < SDIM) {
        const float* p = states + ((size_t)n * BATCH + b0) * SDIM + f;
        #pragma unroll 4
        for (int r = 0; r < RPS; ++r) { float v = p[(size_t)r * SDIM]; s += v; s2 += v * v; }
    } else {
        const float* p = actions + ((size_t)n * BATCH + b0) * ADIM + (f - SDIM);
        #pragma unroll 4
        for (int r = 0; r < RPS; ++r) { float v = p[(size_t)r * ADIM]; s += v; s2 += v * v; }
    }
    atomicAdd(&sum[n * SADIM + f], s);
    atomicAdd(&ssq[n * SADIM + f], s2);
}

__global__ void k_finalize(const float* __restrict__ sum, const float* __restrict__ ssq,
                           float* __restrict__ mean, float* __restrict__ istd) {
    int i = blockIdx.x * blockDim.x + threadIdx.x;
    if (i >= NAG * SADIM) return;
    float m = sum[i] * (1.f / BATCH);
    float v = ssq[i] * (1.f / BATCH) - m * m;
    mean[i] = m;
    istd[i] = rsqrtf(v + 1e-5f);
}

// Wcomb[n][i][j]: j<256 -> Wenc[n][i][j]*istd(i); j>=256 -> (i<512 ? Ws[n][i][j-256]*istd : 0)
__global__ void k_prep_wcomb(const float* __restrict__ Wenc, const float* __restrict__ Ws,
                             const float* __restrict__ istd, float* __restrict__ Wcomb) {
    size_t idx = (size_t)blockIdx.x * blockDim.x + threadIdx.x;
    if (idx >= (size_t)NAG * SADIM * 512) return;
    int j = (int)(idx % 512);
    int i = (int)((idx / 512) % SADIM);
    int n = (int)(idx / (512 * SADIM));
    float is = istd[n * SADIM + i];
    float v;
    if (j < HDIM) v = Wenc[((size_t)n * SADIM + i) * HDIM + j] * is;
    else          v = (i < SDIM) ? Ws[((size_t)n * SDIM + i) * HDIM + (j - HDIM)] * is : 0.f;
    Wcomb[idx] = v;
}

// bcomb[n][j]: j<256 -> benc - sum_i m*istd*Wenc; j>=256 -> bs - sum_{i<512} m*istd*Ws
__global__ void k_biasfold(const float* __restrict__ benc, const float* __restrict__ bs,
                           const float* __restrict__ Wenc, const float* __restrict__ Ws,
                           const float* __restrict__ mean, const float* __restrict__ istd,
                           float* __restrict__ bcomb) {
    int idx = blockIdx.x * blockDim.x + threadIdx.x;
    if (idx >= NAG * 512) return;
    int n = idx / 512, j = idx % 512;
    float acc;
    if (j < HDIM) {
        acc = benc[n * HDIM + j];
        for (int i = 0; i < SADIM; ++i)
            acc -= mean[n * SADIM + i] * istd[n * SADIM + i] *
                   Wenc[((size_t)n * SADIM + i) * HDIM + j];
    } else {
        int jj = j - HDIM;
        acc = bs[n * HDIM + jj];
        for (int i = 0; i < SDIM; ++i)
            acc -= mean[n * SADIM + i] * istd[n * SADIM + i] *
                   Ws[((size_t)n * SDIM + i) * HDIM + jj];
    }
    bcomb[idx] = acc;
}

// Wkv[h][j] (256x512): j<256 -> Wk[e][h][d]; j>=256 -> Wv[e][h][d]  (e=j/16,d=j%16)
// Wselp[h][j] (256x256): Wsel[e][h][d]
__global__ void k_prep_proj(const float* __restrict__ Wk, const float* __restrict__ Wv,
                            const float* __restrict__ Wsel,
                            float* __restrict__ Wkv, float* __restrict__ Wselp) {
    int idx = blockIdx.x * blockDim.x + threadIdx.x;
    if (idx < 256 * 512) {
        int h = idx / 512, j = idx % 512;
        int jj = (j < 256) ? j : j - 256;
        int e = jj >> 4, d = jj & 15;
        const float* src = (j < 256) ? Wk : Wv;
        Wkv[idx] = src[((size_t)e * HDIM + h) * DHEAD + d];
    } else if (idx < 256 * 512 + 256 * 256) {
        int t = idx - 256 * 512;
        int h = t / 256, j = t % 256;
        int e = j >> 4, d = j & 15;
        Wselp[t] = Wsel[((size_t)e * HDIM + h) * DHEAD + d];
    }
}

// Wc1p[n][k][j]: k<256 -> Wc1[n][256+k][j] (other rows); else Wc1[n][k-256][j] (s_enc rows)
__global__ void k_prep_wc1p(const float* __restrict__ Wc1, float* __restrict__ Wc1p) {
    size_t idx = (size_t)blockIdx.x * blockDim.x + threadIdx.x;
    if (idx >= (size_t)NAG * 512 * 256) return;
    int j = (int)(idx % 256);
    int k = (int)((idx / 256) % 512);
    int n = (int)(idx / (512 * 256));
    int sk = (k < 256) ? (k + 256) : (k - 256);
    Wc1p[idx] = Wc1[((size_t)n * 512 + sk) * 256 + j];
}

// ---------------------------------------------------------------------------
// Generic 64x64-tile fp32 GEMM with FFMA2 inner loop.
// M fixed = 131072 rows (agent = row >> 15). W row-major [K][ldw] (+agent stride).
// Columns >= special_col0 get bias[(col-special_col0)] + leaky-relu(0.01).
// ---------------------------------------------------------------------------
__global__ void __launch_bounds__(256)
k_gemm(const float* __restrict__ A, int lda, int aoff,
       const float* __restrict__ A2, int lda2, int ksplit,
       const float* __restrict__ W, size_t w_astride, int ldw,
       const float* __restrict__ bias, int bias_astride, int special_col0,
       float* __restrict__ C, int ldc, int coff, int K)
{
    __shared__ float As[16][64];
    __shared__ float Bs[16][64];
    int tid = threadIdx.x;
    int bx = blockIdx.x, by = blockIdx.y;
    int r0 = by * 64;
    int agent = r0 >> 15;
    const float* Wg = W + (size_t)agent * w_astride + bx * 64;
    int tx = tid & 15, ty = tid >> 4;

    unsigned long long acc[4][2];
    #pragma unroll
    for (int i = 0; i < 4; ++i) { acc[i][0] = 0ull; acc[i][1] = 0ull; }

    int lm = tid >> 2;            // A tile row 0..63
    int lk = (tid & 3) * 4;       // A tile k  0,4,8,12
    int wk = tid >> 4;            // W tile row 0..15
    int wc = (tid & 15) * 4;      // W tile col

    for (int kt = 0; kt < K; kt += 16) {
        int kc = kt + lk;
        const float* src;
        size_t off;
        if (kc < ksplit) { src = A;  off = (size_t)(r0 + lm) * lda + aoff + kc; }
        else             { src = A2; off = (size_t)(r0 + lm) * lda2 + (kc - ksplit); }
        float4 av = *(const float4*)(src + off);
        As[lk + 0][lm] = av.x; As[lk + 1][lm] = av.y;
        As[lk + 2][lm] = av.z; As[lk + 3][lm] = av.w;

        float4 wv = *(const float4*)(Wg + (size_t)(kt + wk) * ldw + wc);
        *(float4*)&Bs[wk][wc] = wv;
        __syncthreads();

        #pragma unroll
        for (int k = 0; k < 16; ++k) {
            float4 a4 = *(const float4*)&As[k][ty * 4];
            ulonglong2 b2 = *(const ulonglong2*)&Bs[k][tx * 4];
            unsigned long long a0 = pack2(a4.x, a4.x);
            unsigned long long a1 = pack2(a4.y, a4.y);
            unsigned long long a2 = pack2(a4.z, a4.z);
            unsigned long long a3 = pack2(a4.w, a4.w);
            acc[0][0] = fma2(a0, b2.x, acc[0][0]); acc[0][1] = fma2(a0, b2.y, acc[0][1]);
            acc[1][0] = fma2(a1, b2.x, acc[1][0]); acc[1][1] = fma2(a1, b2.y, acc[1][1]);
            acc[2][0] = fma2(a2, b2.x, acc[2][0]); acc[2][1] = fma2(a2, b2.y, acc[2][1]);
            acc[3][0] = fma2(a3, b2.x, acc[3][0]); acc[3][1] = fma2(a3, b2.y, acc[3][1]);
        }
        __syncthreads();
    }

    #pragma unroll
    for (int i = 0; i < 4; ++i) {
        int row = r0 + ty * 4 + i;
        float out[4];
        float2 p0 = unpack2(acc[i][0]);
        float2 p1 = unpack2(acc[i][1]);
        out[0] = p0.x; out[1] = p0.y; out[2] = p1.x; out[3] = p1.y;
        #pragma unroll
        for (int j = 0; j < 4; ++j) {
            int gcol = bx * 64 + tx * 4 + j;
            float v = out[j];
            if (gcol >= special_col0) {
                v += bias[(size_t)agent * bias_astride + (gcol - special_col0)];
                v = v > 0.f ? v : 0.01f * v;
            }
            out[j] = v;
        }
        *(float4*)(C + (size_t)row * ldc + coff + bx * 64 + tx * 4) = *(float4*)out;
    }
}

// ---------------------------------------------------------------------------
// Attention: per (b, head e): logits[i][j] = sel_i . key_j / 4, self-masked
// softmax over j, other[i][b][e*16+d] = sum_j p * val_j[d]. 4 b's per block.
// ---------------------------------------------------------------------------
__global__ void __launch_bounds__(256)
k_attn(const float* __restrict__ kvs, float* __restrict__ enc) {
    __shared__ float sh[4][4][768];    // [b_local][agent][keys|vals|sel] = 48KB
    int tid = threadIdx.x;
    int b0 = blockIdx.x * 4;
    for (int t = tid; t < 3072; t += 256) {
        int row = t / 192, c4 = t % 192;
        int bl = row >> 2, ag = row & 3;
        float4 v = *(const float4*)(kvs + ((size_t)ag * BATCH + b0 + bl) * 768 + c4 * 4);
        *(float4*)&sh[bl][ag][c4 * 4] = v;
    }
    __syncthreads();

    int bl = tid >> 6, rem = tid & 63, e = rem >> 2, i = rem & 3;
    const float* selp = &sh[bl][i][512 + e * 16];
    float logits[4];
    #pragma unroll
    for (int j = 0; j < 4; ++j) {
        const float* kp = &sh[bl][j][e * 16];
        float acc = 0.f;
        #pragma unroll
        for (int d = 0; d < 16; ++d) acc += selp[d] * kp[d];
        logits[j] = acc * 0.25f;
    }
    logits[i] = -1e9f;
    float mx = fmaxf(fmaxf(logits[0], logits[1]), fmaxf(logits[2], logits[3]));
    float p[4], s = 0.f;
    #pragma unroll
    for (int j = 0; j < 4; ++j) { p[j] = __expf(logits[j] - mx); s += p[j]; }
    float inv = 1.f / s;
    float out[16];
    #pragma unroll
    for (int d = 0; d < 16; ++d) out[d] = 0.f;
    #pragma unroll
    for (int j = 0; j < 4; ++j) {
        float pj = p[j] * inv;
        const float* vp = &sh[bl][j][256 + e * 16];
        #pragma unroll
        for (int d = 0; d < 16; ++d) out[d] += pj * vp[d];
    }
    float* dst = enc + ((size_t)i * BATCH + b0 + bl) * 512 + e * 16;
    #pragma unroll
    for (int d = 0; d < 16; d += 4)
        *(float4*)(dst + d) = make_float4(out[d], out[d + 1], out[d + 2], out[d + 3]);
}

// ---------------------------------------------------------------------------
// fc2 + argmax gather: one warp per row.
// ---------------------------------------------------------------------------
__global__ void __launch_bounds__(256)
k_fc2(const float* __restrict__ actions, const float* __restrict__ Wc2,
      const float* __restrict__ bc2, const float* __restrict__ H,
      float* __restrict__ out) {
    int row = blockIdx.x * 8 + (threadIdx.x >> 5);
    int lane = threadIdx.x & 31;
    int n = row >> 15;
    const float* arow = actions + (size_t)row * ADIM;
    float bestv = -1e30f; int besti = ADIM;
    for (int c = lane; c < ADIM; c += 32) {
        float v = arow[c];
        if (v > bestv || (v == bestv && c < besti)) { bestv = v; besti = c; }
    }
    #pragma unroll
    for (int off = 16; off; off >>= 1) {
        float ov = __shfl_down_sync(0xffffffffu, bestv, off);
        int   oi = __shfl_down_sync(0xffffffffu, besti, off);
        if (ov > bestv || (ov == bestv && oi < besti)) { bestv = ov; besti = oi; }
    }
    besti = __shfl_sync(0xffffffffu, besti, 0);

    const float* hrow = H + (size_t)row * HDIM;
    const float* wcol = Wc2 + (size_t)n * HDIM * ADIM + besti;
    float acc = 0.f;
    for (int k = lane; k < HDIM; k += 32)
        acc += hrow[k] * wcol[(size_t)k * ADIM];
    #pragma unroll
    for (int off = 16; off; off >>= 1)
        acc += __shfl_down_sync(0xffffffffu, acc, off);
    if (lane == 0) out[row] = acc + bc2[n * ADIM + besti];
}

// ---------------------------------------------------------------------------
extern "C" void kernel_launch(void* const* d_in, const int* in_sizes, int n_in,
                              void* d_out, int out_size) {
    (void)in_sizes; (void)n_in; (void)out_size;
    const float* states  = (const float*)d_in[0];
    const float* actions = (const float*)d_in[1];
    const float* Wenc    = (const float*)d_in[2];
    const float* benc    = (const float*)d_in[3];
    const float* Ws      = (const float*)d_in[4];
    const float* bs      = (const float*)d_in[5];
    const float* Wk      = (const float*)d_in[6];
    const float* Wsel    = (const float*)d_in[7];
    const float* Wv      = (const float*)d_in[8];
    const float* bv      = (const float*)d_in[9];
    const float* Wc1     = (const float*)d_in[10];
    const float* bc1     = (const float*)d_in[11];
    const float* Wc2     = (const float*)d_in[12];
    const float* bc2     = (const float*)d_in[13];
    float* out = (float*)d_out;

    float* S = nullptr;
    cudaGetSymbolAddress((void**)&S, g_scratch);
    float* SUM   = S + O_SUM;
    float* SSQ   = S + O_SSQ;
    float* MEAN  = S + O_MEAN;
    float* ISTD  = S + O_ISTD;
    float* BCOMB = S + O_BCOMB;
    float* WCOMB = S + O_WCOMB;
    float* WKV   = S + O_WKV;
    float* WSEL  = S + O_WSEL;
    float* WC1P  = S + O_WC1P;
    float* ENC   = S + O_ENC;
    float* KVS   = S + O_KVS;
    float* HBUF  = S + O_H;

    // 1) batch stats
    k_zero<<<(4608 + 255) / 256, 256>>>(SUM, 4608);   // SUM + SSQ contiguous
    k_stats<<<dim3(4, 64), 576>>>(states, actions, SUM, SSQ);
    k_finalize<<<(2304 + 255) / 256, 256>>>(SUM, SSQ, MEAN, ISTD);

    // 2) weight prep (BN fold + head-concat + fc1 row-swap)
    k_prep_wcomb<<<(NAG * SADIM * 512 + 255) / 256, 256>>>(Wenc, Ws, ISTD, WCOMB);
    k_biasfold<<<(NAG * 512 + 255) / 256, 256>>>(benc, bs, Wenc, Ws, MEAN, ISTD, BCOMB);
    k_prep_proj<<<(256 * 512 + 256 * 256 + 255) / 256, 256>>>(Wk, Wv, Wsel, WKV, WSEL);
    k_prep_wc1p<<<(NAG * 512 * 256 + 255) / 256, 256>>>(Wc1, WC1P);

    // 3) encoder GEMM: [states|actions] (K=576) -> ENC [sa_enc|s_enc] (N=512)
    k_gemm<<<dim3(8, ROWS / 64), 256>>>(states, SDIM, 0, actions, ADIM, SDIM,
                                        WCOMB, (size_t)SADIM * 512, 512,
                                        BCOMB, 512, 0,
                                        ENC, 512, 0, SADIM);
    // 4) keys|vals: sa_enc (K=256) -> KVS cols 0..511 (vals get bv + lrelu)
    k_gemm<<<dim3(8, ROWS / 64), 256>>>(ENC, 512, 0, ENC, 512, 256,
                                        WKV, 0, 512,
                                        bv, 0, 256,
                                        KVS, 768, 0, 256);
    //    sel: s_enc (K=256) -> KVS cols 512..767 (plain)
    k_gemm<<<dim3(4, ROWS / 64), 256>>>(ENC, 512, 256, ENC, 512, 256,
                                        WSEL, 0, 256,
                                        bv, 0, 1 << 30,
                                        KVS, 768, 512, 256);
    // 5) attention -> other written into ENC cols 0..255
    k_attn<<<BATCH / 4, 256>>>(KVS, ENC);

    // 6) critic fc1: ENC [other|s_enc] (K=512) @ Wc1p -> H (bc1 + lrelu)
    k_gemm<<<dim3(4, ROWS / 64), 256>>>(ENC, 512, 0, ENC, 512, 512,
                                        WC1P, (size_t)512 * 256, 256,
                                        bc1, 256, 0,
                                        HBUF, 256, 0, 512);
    // 7) fc2 + argmax gather
    k_fc2<<<ROWS / 8, 256>>>(actions, Wc2, bc2, HBUF, out);
}

// round 2
// speedup vs baseline: 2.2603x; 2.2603x over previous
#include <cuda_runtime.h>
#include <cuda_bf16.h>

// ---------------------------------------------------------------------------
// AttentionCritic: N=4 agents, B=32768, S=512, A=64, H=256, NH=16, D=16
// Round 2: all four large GEMMs run on tensor cores (mma.sync m16n8k8 tf32,
// explicit rna rounding at the gmem->smem stage). Everything else unchanged.
// ---------------------------------------------------------------------------

#define NAG   4
#define BATCH 32768
#define ROWS  (NAG * BATCH)       // 131072
#define SDIM  512
#define ADIM  64
#define SADIM 576
#define HDIM  256
#define NHEAD 16
#define DHEAD 16

// ---- scratch layout (floats) ----
constexpr size_t O_SUM   = 0;             // 2304 (4*576)
constexpr size_t O_SSQ   = 2304;          // 2304
constexpr size_t O_MEAN  = 4608;          // 2304
constexpr size_t O_ISTD  = 6912;          // 2304
constexpr size_t O_BCOMB = 9216;          // 2048 (4*512)
constexpr size_t O_WCOMB = 11264;         // 4*576*512 = 1179648
constexpr size_t O_WKV   = 1190912;       // 256*512   = 131072
constexpr size_t O_WSEL  = 1321984;       // 256*256   = 65536
constexpr size_t O_WC1P  = 1387520;       // 4*512*256 = 524288
constexpr size_t O_ENC   = 1911808;       // 131072*512 = 67108864
constexpr size_t O_KVS   = 69020672;      // 131072*768 = 100663296
constexpr size_t O_H     = 169683968;     // 131072*256 = 33554432
constexpr size_t SCRATCH_FLOATS = 203238400;

__device__ float g_scratch[SCRATCH_FLOATS];

// ---------------------------------------------------------------------------
__device__ __forceinline__ unsigned f2tf32(float x) {
    unsigned r;
    asm("cvt.rna.tf32.f32 %0, %1;" : "=r"(r) : "f"(x));
    return r;
}

__device__ __forceinline__ void mma_tf32(float* d, const unsigned* a, const unsigned* b) {
    asm("mma.sync.aligned.m16n8k8.row.col.f32.tf32.tf32.f32 "
        "{%0,%1,%2,%3}, {%4,%5,%6,%7}, {%8,%9}, {%0,%1,%2,%3};"
        : "+f"(d[0]), "+f"(d[1]), "+f"(d[2]), "+f"(d[3])
        : "r"(a[0]), "r"(a[1]), "r"(a[2]), "r"(a[3]), "r"(b[0]), "r"(b[1]));
}

// ---------------------------------------------------------------------------
__global__ void k_zero(float* p, int n) {
    int i = blockIdx.x * blockDim.x + threadIdx.x;
    if (i < n) p[i] = 0.f;
}

// grid (4, 64), block 576. thread f: feature column (states 0..511, actions 512..575)
__global__ void k_stats(const float* __restrict__ states,
                        const float* __restrict__ actions,
                        float* __restrict__ sum, float* __restrict__ ssq) {
    int n = blockIdx.x, slab = blockIdx.y, f = threadIdx.x;
    const int RPS = BATCH / 64;   // 512 rows per slab
    int b0 = slab * RPS;
    float s = 0.f, s2 = 0.f;
    if (f < SDIM) {
        const float* p = states + ((size_t)n * BATCH + b0) * SDIM + f;
        #pragma unroll 4
        for (int r = 0; r < RPS; ++r) { float v = p[(size_t)r * SDIM]; s += v; s2 += v * v; }
    } else {
        const float* p = actions + ((size_t)n * BATCH + b0) * ADIM + (f - SDIM);
        #pragma unroll 4
        for (int r = 0; r < RPS; ++r) { float v = p[(size_t)r * ADIM]; s += v; s2 += v * v; }
    }
    atomicAdd(&sum[n * SADIM + f], s);
    atomicAdd(&ssq[n * SADIM + f], s2);
}

__global__ void k_finalize(const float* __restrict__ sum, const float* __restrict__ ssq,
                           float* __restrict__ mean, float* __restrict__ istd) {
    int i = blockIdx.x * blockDim.x + threadIdx.x;
    if (i >= NAG * SADIM) return;
    float m = sum[i] * (1.f / BATCH);
    float v = ssq[i] * (1.f / BATCH) - m * m;
    mean[i] = m;
    istd[i] = rsqrtf(v + 1e-5f);
}

// Wcomb[n][i][j]: j<256 -> Wenc[n][i][j]*istd(i); j>=256 -> (i<512 ? Ws[n][i][j-256]*istd : 0)
__global__ void k_prep_wcomb(const float* __restrict__ Wenc, const float* __restrict__ Ws,
                             const float* __restrict__ istd, float* __restrict__ Wcomb) {
    size_t idx = (size_t)blockIdx.x * blockDim.x + threadIdx.x;
    if (idx >= (size_t)NAG * SADIM * 512) return;
    int j = (int)(idx % 512);
    int i = (int)((idx / 512) % SADIM);
    int n = (int)(idx / (512 * SADIM));
    float is = istd[n * SADIM + i];
    float v;
    if (j < HDIM) v = Wenc[((size_t)n * SADIM + i) * HDIM + j] * is;
    else          v = (i < SDIM) ? Ws[((size_t)n * SDIM + i) * HDIM + (j - HDIM)] * is : 0.f;
    Wcomb[idx] = v;
}

// bcomb[n][j]: j<256 -> benc - sum_i m*istd*Wenc; j>=256 -> bs - sum_{i<512} m*istd*Ws
__global__ void k_biasfold(const float* __restrict__ benc, const float* __restrict__ bs,
                           const float* __restrict__ Wenc, const float* __restrict__ Ws,
                           const float* __restrict__ mean, const float* __restrict__ istd,
                           float* __restrict__ bcomb) {
    int idx = blockIdx.x * blockDim.x + threadIdx.x;
    if (idx >= NAG * 512) return;
    int n = idx / 512, j = idx % 512;
    float acc;
    if (j < HDIM) {
        acc = benc[n * HDIM + j];
        for (int i = 0; i < SADIM; ++i)
            acc -= mean[n * SADIM + i] * istd[n * SADIM + i] *
                   Wenc[((size_t)n * SADIM + i) * HDIM + j];
    } else {
        int jj = j - HDIM;
        acc = bs[n * HDIM + jj];
        for (int i = 0; i < SDIM; ++i)
            acc -= mean[n * SADIM + i] * istd[n * SADIM + i] *
                   Ws[((size_t)n * SDIM + i) * HDIM + jj];
    }
    bcomb[idx] = acc;
}

// Wkv[h][j] (256x512): j<256 -> Wk[e][h][d]; j>=256 -> Wv[e][h][d]  (e=j/16,d=j%16)
// Wselp[h][j] (256x256): Wsel[e][h][d]
__global__ void k_prep_proj(const float* __restrict__ Wk, const float* __restrict__ Wv,
                            const float* __restrict__ Wsel,
                            float* __restrict__ Wkv, float* __restrict__ Wselp) {
    int idx = blockIdx.x * blockDim.x + threadIdx.x;
    if (idx < 256 * 512) {
        int h = idx / 512, j = idx % 512;
        int jj = (j < 256) ? j : j - 256;
        int e = jj >> 4, d = jj & 15;
        const float* src = (j < 256) ? Wk : Wv;
        Wkv[idx] = src[((size_t)e * HDIM + h) * DHEAD + d];
    } else if (idx < 256 * 512 + 256 * 256) {
        int t = idx - 256 * 512;
        int h = t / 256, j = t % 256;
        int e = j >> 4, d = j & 15;
        Wselp[t] = Wsel[((size_t)e * HDIM + h) * DHEAD + d];
    }
}

// Wc1p[n][k][j]: k<256 -> Wc1[n][256+k][j] (other rows); else Wc1[n][k-256][j] (s_enc rows)
__global__ void k_prep_wc1p(const float* __restrict__ Wc1, float* __restrict__ Wc1p) {
    size_t idx = (size_t)blockIdx.x * blockDim.x + threadIdx.x;
    if (idx >= (size_t)NAG * 512 * 256) return;
    int j = (int)(idx % 256);
    int k = (int)((idx / 256) % 512);
    int n = (int)(idx / (512 * 256));
    int sk = (k < 256) ? (k + 256) : (k - 256);
    Wc1p[idx] = Wc1[((size_t)n * 512 + sk) * 256 + j];
}

// ---------------------------------------------------------------------------
// Tensor-core GEMM: 128x128 block tile, 8 warps (2M x 4N), warp tile 64x32,
// mma.sync m16n8k8 tf32 (rna-rounded at smem store), double-buffered K=16.
// A rows come from [A | A2] split at ksplit (stage-uniform: ksplit % 16 == 0).
// Columns >= special_col0 get bias + leaky-relu(0.01).
// ---------------------------------------------------------------------------
__global__ void __launch_bounds__(256)
k_gemm_tc(const float* __restrict__ A, int lda, int aoff,
          const float* __restrict__ A2, int lda2, int ksplit,
          const float* __restrict__ W, size_t w_astride, int ldw,
          const float* __restrict__ bias, int bias_astride, int special_col0,
          float* __restrict__ C, int ldc, int coff, int K)
{
    __shared__ float As[2][128][20];   // pitch 20 -> conflict-free frag loads
    __shared__ float Bs[2][16][136];   // pitch 136 -> conflict-free frag loads

    const int tid  = threadIdx.x;
    const int lane = tid & 31;
    const int wid  = tid >> 5;
    const int warpM = wid & 1;         // 0..1  (64-row slices)
    const int warpN = wid >> 1;        // 0..3  (32-col slices)
    const int lq = lane >> 2;          // 0..7
    const int lr = lane & 3;           // 0..3

    const int bx = blockIdx.x;
    const int r0 = blockIdx.y * 128;
    const int agent = r0 >> 15;
    const float* Wg = W + (size_t)agent * w_astride + bx * 128;

    // gmem-load mapping
    const int arow = tid >> 1;          // 0..127
    const int acol = (tid & 1) * 8;     // 0 or 8
    const int brow = tid >> 4;          // 0..15
    const int bcol = (tid & 15) * 8;    // 0..120

    float acc[4][4][4];
    #pragma unroll
    for (int mt = 0; mt < 4; ++mt)
        #pragma unroll
        for (int nt = 0; nt < 4; ++nt)
            #pragma unroll
            for (int i = 0; i < 4; ++i) acc[mt][nt][i] = 0.f;

    float4 ra0, ra1, rb0, rb1;

    auto ldg_stage = [&](int kt) {
        const float* ap;
        if (kt < ksplit) ap = A  + (size_t)(r0 + arow) * lda  + aoff + kt + acol;
        else             ap = A2 + (size_t)(r0 + arow) * lda2 + (kt - ksplit) + acol;
        ra0 = *(const float4*)ap;
        ra1 = *(const float4*)(ap + 4);
        const float* bp = Wg + (size_t)(kt + brow) * ldw + bcol;
        rb0 = *(const float4*)bp;
        rb1 = *(const float4*)(bp + 4);
    };
    auto sts_stage = [&](int buf) {
        float* as = &As[buf][arow][acol];
        as[0] = __uint_as_float(f2tf32(ra0.x)); as[1] = __uint_as_float(f2tf32(ra0.y));
        as[2] = __uint_as_float(f2tf32(ra0.z)); as[3] = __uint_as_float(f2tf32(ra0.w));
        as[4] = __uint_as_float(f2tf32(ra1.x)); as[5] = __uint_as_float(f2tf32(ra1.y));
        as[6] = __uint_as_float(f2tf32(ra1.z)); as[7] = __uint_as_float(f2tf32(ra1.w));
        float* bsp = &Bs[buf][brow][bcol];
        bsp[0] = __uint_as_float(f2tf32(rb0.x)); bsp[1] = __uint_as_float(f2tf32(rb0.y));
        bsp[2] = __uint_as_float(f2tf32(rb0.z)); bsp[3] = __uint_as_float(f2tf32(rb0.w));
        bsp[4] = __uint_as_float(f2tf32(rb1.x)); bsp[5] = __uint_as_float(f2tf32(rb1.y));
        bsp[6] = __uint_as_float(f2tf32(rb1.z)); bsp[7] = __uint_as_float(f2tf32(rb1.w));
    };
    auto compute = [&](int buf) {
        #pragma unroll
        for (int k0 = 0; k0 < 16; k0 += 8) {
            unsigned af[4][4], bf[4][2];
            #pragma unroll
            for (int mt = 0; mt < 4; ++mt) {
                int r = warpM * 64 + mt * 16 + lq;
                af[mt][0] = __float_as_uint(As[buf][r    ][k0 + lr    ]);
                af[mt][1] = __float_as_uint(As[buf][r + 8][k0 + lr    ]);
                af[mt][2] = __float_as_uint(As[buf][r    ][k0 + lr + 4]);
                af[mt][3] = __float_as_uint(As[buf][r + 8][k0 + lr + 4]);
            }
            #pragma unroll
            for (int nt = 0; nt < 4; ++nt) {
                int nn = warpN * 32 + nt * 8 + lq;
                bf[nt][0] = __float_as_uint(Bs[buf][k0 + lr    ][nn]);
                bf[nt][1] = __float_as_uint(Bs[buf][k0 + lr + 4][nn]);
            }
            #pragma unroll
            for (int mt = 0; mt < 4; ++mt)
                #pragma unroll
                for (int nt = 0; nt < 4; ++nt)
                    mma_tf32(acc[mt][nt], af[mt], bf[nt]);
        }
    };

    // prologue
    ldg_stage(0);
    sts_stage(0);
    __syncthreads();

    int cur = 0;
    for (int kt = 16; kt < K; kt += 16) {
        ldg_stage(kt);
        compute(cur);
        sts_stage(cur ^ 1);
        __syncthreads();
        cur ^= 1;
    }
    compute(cur);

    // epilogue: bias + leaky-relu on cols >= special_col0, float2 stores
    #pragma unroll
    for (int mt = 0; mt < 4; ++mt) {
        int r = r0 + warpM * 64 + mt * 16 + lq;
        #pragma unroll
        for (int nt = 0; nt < 4; ++nt) {
            int gc = bx * 128 + warpN * 32 + nt * 8 + 2 * lr;
            float v0 = acc[mt][nt][0], v1 = acc[mt][nt][1];
            float v2 = acc[mt][nt][2], v3 = acc[mt][nt][3];
            if (gc >= special_col0) {
                float b0 = bias[(size_t)agent * bias_astride + (gc     - special_col0)];
                float b1 = bias[(size_t)agent * bias_astride + (gc + 1 - special_col0)];
                v0 += b0; v1 += b1; v2 += b0; v3 += b1;
                v0 = v0 > 0.f ? v0 : 0.01f * v0;
                v1 = v1 > 0.f ? v1 : 0.01f * v1;
                v2 = v2 > 0.f ? v2 : 0.01f * v2;
                v3 = v3 > 0.f ? v3 : 0.01f * v3;
            }
            *(float2*)(C + (size_t)r * ldc + coff + gc)       = make_float2(v0, v1);
            *(float2*)(C + (size_t)(r + 8) * ldc + coff + gc) = make_float2(v2, v3);
        }
    }
}

// ---------------------------------------------------------------------------
// Attention: per (b, head e): logits[i][j] = sel_i . key_j / 4, self-masked
// softmax over j, other[i][b][e*16+d] = sum_j p * val_j[d]. 4 b's per block.
// ---------------------------------------------------------------------------
__global__ void __launch_bounds__(256)
k_attn(const float* __restrict__ kvs, float* __restrict__ enc) {
    __shared__ float sh[4][4][768];    // [b_local][agent][keys|vals|sel] = 48KB
    int tid = threadIdx.x;
    int b0 = blockIdx.x * 4;
    for (int t = tid; t < 3072; t += 256) {
        int row = t / 192, c4 = t % 192;
        int bl = row >> 2, ag = row & 3;
        float4 v = *(const float4*)(kvs + ((size_t)ag * BATCH + b0 + bl) * 768 + c4 * 4);
        *(float4*)&sh[bl][ag][c4 * 4] = v;
    }
    __syncthreads();

    int bl = tid >> 6, rem = tid & 63, e = rem >> 2, i = rem & 3;
    const float* selp = &sh[bl][i][512 + e * 16];
    float logits[4];
    #pragma unroll
    for (int j = 0; j < 4; ++j) {
        const float* kp = &sh[bl][j][e * 16];
        float acc = 0.f;
        #pragma unroll
        for (int d = 0; d < 16; ++d) acc += selp[d] * kp[d];
        logits[j] = acc * 0.25f;
    }
    logits[i] = -1e9f;
    float mx = fmaxf(fmaxf(logits[0], logits[1]), fmaxf(logits[2], logits[3]));
    float p[4], s = 0.f;
    #pragma unroll
    for (int j = 0; j < 4; ++j) { p[j] = __expf(logits[j] - mx); s += p[j]; }
    float inv = 1.f / s;
    float out[16];
    #pragma unroll
    for (int d = 0; d < 16; ++d) out[d] = 0.f;
    #pragma unroll
    for (int j = 0; j < 4; ++j) {
        float pj = p[j] * inv;
        const float* vp = &sh[bl][j][256 + e * 16];
        #pragma unroll
        for (int d = 0; d < 16; ++d) out[d] += pj * vp[d];
    }
    float* dst = enc + ((size_t)i * BATCH + b0 + bl) * 512 + e * 16;
    #pragma unroll
    for (int d = 0; d < 16; d += 4)
        *(float4*)(dst + d) = make_float4(out[d], out[d + 1], out[d + 2], out[d + 3]);
}

// ---------------------------------------------------------------------------
// fc2 + argmax gather: one warp per row.
// ---------------------------------------------------------------------------
__global__ void __launch_bounds__(256)
k_fc2(const float* __restrict__ actions, const float* __restrict__ Wc2,
      const float* __restrict__ bc2, const float* __restrict__ H,
      float* __restrict__ out) {
    int row = blockIdx.x * 8 + (threadIdx.x >> 5);
    int lane = threadIdx.x & 31;
    int n = row >> 15;
    const float* arow = actions + (size_t)row * ADIM;
    float bestv = -1e30f; int besti = ADIM;
    for (int c = lane; c < ADIM; c += 32) {
        float v = arow[c];
        if (v > bestv || (v == bestv && c < besti)) { bestv = v; besti = c; }
    }
    #pragma unroll
    for (int off = 16; off; off >>= 1) {
        float ov = __shfl_down_sync(0xffffffffu, bestv, off);
        int   oi = __shfl_down_sync(0xffffffffu, besti, off);
        if (ov > bestv || (ov == bestv && oi < besti)) { bestv = ov; besti = oi; }
    }
    besti = __shfl_sync(0xffffffffu, besti, 0);

    const float* hrow = H + (size_t)row * HDIM;
    const float* wcol = Wc2 + (size_t)n * HDIM * ADIM + besti;
    float acc = 0.f;
    for (int k = lane; k < HDIM; k += 32)
        acc += hrow[k] * wcol[(size_t)k * ADIM];
    #pragma unroll
    for (int off = 16; off; off >>= 1)
        acc += __shfl_down_sync(0xffffffffu, acc, off);
    if (lane == 0) out[row] = acc + bc2[n * ADIM + besti];
}

// ---------------------------------------------------------------------------
extern "C" void kernel_launch(void* const* d_in, const int* in_sizes, int n_in,
                              void* d_out, int out_size) {
    (void)in_sizes; (void)n_in; (void)out_size;
    const float* states  = (const float*)d_in[0];
    const float* actions = (const float*)d_in[1];
    const float* Wenc    = (const float*)d_in[2];
    const float* benc    = (const float*)d_in[3];
    const float* Ws      = (const float*)d_in[4];
    const float* bs      = (const float*)d_in[5];
    const float* Wk      = (const float*)d_in[6];
    const float* Wsel    = (const float*)d_in[7];
    const float* Wv      = (const float*)d_in[8];
    const float* bv      = (const float*)d_in[9];
    const float* Wc1     = (const float*)d_in[10];
    const float* bc1     = (const float*)d_in[11];
    const float* Wc2     = (const float*)d_in[12];
    const float* bc2     = (const float*)d_in[13];
    float* out = (float*)d_out;

    float* S = nullptr;
    cudaGetSymbolAddress((void**)&S, g_scratch);
    float* SUM   = S + O_SUM;
    float* SSQ   = S + O_SSQ;
    float* MEAN  = S + O_MEAN;
    float* ISTD  = S + O_ISTD;
    float* BCOMB = S + O_BCOMB;
    float* WCOMB = S + O_WCOMB;
    float* WKV   = S + O_WKV;
    float* WSEL  = S + O_WSEL;
    float* WC1P  = S + O_WC1P;
    float* ENC   = S + O_ENC;
    float* KVS   = S + O_KVS;
    float* HBUF  = S + O_H;

    const int BIG = 1 << 30;

    // 1) batch stats
    k_zero<<<(4608 + 255) / 256, 256>>>(SUM, 4608);   // SUM + SSQ contiguous
    k_stats<<<dim3(4, 64), 576>>>(states, actions, SUM, SSQ);
    k_finalize<<<(2304 + 255) / 256, 256>>>(SUM, SSQ, MEAN, ISTD);

    // 2) weight prep (BN fold + head-concat + fc1 row-swap)
    k_prep_wcomb<<<(NAG * SADIM * 512 + 255) / 256, 256>>>(Wenc, Ws, ISTD, WCOMB);
    k_biasfold<<<(NAG * 512 + 255) / 256, 256>>>(benc, bs, Wenc, Ws, MEAN, ISTD, BCOMB);
    k_prep_proj<<<(256 * 512 + 256 * 256 + 255) / 256, 256>>>(Wk, Wv, Wsel, WKV, WSEL);
    k_prep_wc1p<<<(NAG * 512 * 256 + 255) / 256, 256>>>(Wc1, WC1P);

    // 3) encoder GEMM: [states|actions] (K=576) -> ENC [sa_enc|s_enc] (N=512)
    k_gemm_tc<<<dim3(4, ROWS / 128), 256>>>(states, SDIM, 0, actions, ADIM, SDIM,
                                            WCOMB, (size_t)SADIM * 512, 512,
                                            BCOMB, 512, 0,
                                            ENC, 512, 0, SADIM);
    // 4) keys|vals: sa_enc (K=256) -> KVS cols 0..511 (vals get bv + lrelu)
    k_gemm_tc<<<dim3(4, ROWS / 128), 256>>>(ENC, 512, 0, ENC, 512, BIG,
                                            WKV, 0, 512,
                                            bv, 0, 256,
                                            KVS, 768, 0, 256);
    //    sel: s_enc (K=256) -> KVS cols 512..767 (plain)
    k_gemm_tc<<<dim3(2, ROWS / 128), 256>>>(ENC, 512, 256, ENC, 512, BIG,
                                            WSEL, 0, 256,
                                            bv, 0, BIG,
                                            KVS, 768, 512, 256);
    // 5) attention -> other written into ENC cols 0..255
    k_attn<<<BATCH / 4, 256>>>(KVS, ENC);

    // 6) critic fc1: ENC [other|s_enc] (K=512) @ Wc1p -> H (bc1 + lrelu)
    k_gemm_tc<<<dim3(2, ROWS / 128), 256>>>(ENC, 512, 0, ENC, 512, BIG,
                                            WC1P, (size_t)512 * 256, 256,
                                            bc1, 256, 0,
                                            HBUF, 256, 0, 512);
    // 7) fc2 + argmax gather
    k_fc2<<<ROWS / 8, 256>>>(actions, Wc2, bc2, HBUF, out);
}

// round 4
// speedup vs baseline: 2.4855x; 1.0996x over previous
#include <cuda_runtime.h>
#include <cuda_bf16.h>
#include <cstdint>

// ---------------------------------------------------------------------------
// AttentionCritic: N=4 agents, B=32768, S=512, A=64, H=256, NH=16, D=16
// Round 4: mma.sync tf32 (tcgen05 unavailable: toolchain targets compute_103),
// 4-stage cp.async pipeline, all tf32 rounding pre-applied in memory.
// ---------------------------------------------------------------------------

#define NAG   4
#define BATCH 32768
#define ROWS  (NAG * BATCH)       // 131072
#define SDIM  512
#define ADIM  64
#define SADIM 576
#define HDIM  256

// ---- scratch layout (floats) ----
constexpr size_t O_SUM    = 0;
constexpr size_t O_SSQ    = 2304;
constexpr size_t O_MEAN   = 4608;
constexpr size_t O_ISTD   = 6912;
constexpr size_t O_BCOMB  = 9216;          // 2048
constexpr size_t O_WCOMBT = 11264;         // 4*512*576 = 1179648
constexpr size_t O_WKVT   = 1190912;       // 512*256   = 131072
constexpr size_t O_WSELT  = 1321984;       // 256*256   = 65536
constexpr size_t O_WC1PT  = 1387520;       // 4*256*512 = 524288
constexpr size_t O_ENC    = 1911808;       // 131072*512
constexpr size_t O_KVS    = 69020672;      // 131072*768
constexpr size_t O_H      = 169683968;     // 131072*256
constexpr size_t O_STF    = 203238400;     // 131072*512 (tf32-rounded states)
constexpr size_t O_ATF    = 270347264;     // 131072*64  (tf32-rounded actions)
constexpr size_t SCRATCH_FLOATS = 278735872;

__device__ float g_scratch[SCRATCH_FLOATS];

// ---------------------------------------------------------------------------
__device__ __forceinline__ unsigned f2tf32(float x) {
    unsigned r;
    asm("cvt.rna.tf32.f32 %0, %1;" : "=r"(r) : "f"(x));
    return r;
}
__device__ __forceinline__ float roundtf(float x) { return __uint_as_float(f2tf32(x)); }

__device__ __forceinline__ void mma_tf32(float* d, const unsigned* a, const unsigned* b) {
    asm("mma.sync.aligned.m16n8k8.row.col.f32.tf32.tf32.f32 "
        "{%0,%1,%2,%3}, {%4,%5,%6,%7}, {%8,%9}, {%0,%1,%2,%3};"
        : "+f"(d[0]), "+f"(d[1]), "+f"(d[2]), "+f"(d[3])
        : "r"(a[0]), "r"(a[1]), "r"(a[2]), "r"(a[3]), "r"(b[0]), "r"(b[1]));
}

__device__ __forceinline__ uint32_t smem_u32(const void* p) {
    uint32_t a;
    asm("{ .reg .u64 t; cvta.to.shared.u64 t, %1; cvt.u32.u64 %0, t; }" : "=r"(a) : "l"(p));
    return a;
}
__device__ __forceinline__ void cp_async16(uint32_t dst, const void* src) {
    asm volatile("cp.async.cg.shared.global [%0], [%1], 16;" :: "r"(dst), "l"(src) : "memory");
}
__device__ __forceinline__ void cp_commit() {
    asm volatile("cp.async.commit_group;" ::: "memory");
}
template <int N>
__device__ __forceinline__ void cp_wait() {
    asm volatile("cp.async.wait_group %0;" :: "n"(N) : "memory");
}

// ---------------------------------------------------------------------------
__global__ void k_zero(float* p, int n) {
    int i = blockIdx.x * blockDim.x + threadIdx.x;
    if (i < n) p[i] = 0.f;
}

// tf32-round copy
__global__ void k_round4(const float* __restrict__ in, float* __restrict__ out, size_t n) {
    size_t i = ((size_t)blockIdx.x * blockDim.x + threadIdx.x) * 4;
    if (i >= n) return;
    float4 v = *(const float4*)(in + i);
    v.x = roundtf(v.x); v.y = roundtf(v.y); v.z = roundtf(v.z); v.w = roundtf(v.w);
    *(float4*)(out + i) = v;
}

// grid (4, 64), block 576
__global__ void k_stats(const float* __restrict__ states,
                        const float* __restrict__ actions,
                        float* __restrict__ sum, float* __restrict__ ssq) {
    int n = blockIdx.x, slab = blockIdx.y, f = threadIdx.x;
    const int RPS = BATCH / 64;
    int b0 = slab * RPS;
    float s = 0.f, s2 = 0.f;
    if (f < SDIM) {
        const float* p = states + ((size_t)n * BATCH + b0) * SDIM + f;
        #pragma unroll 4
        for (int r = 0; r < RPS; ++r) { float v = p[(size_t)r * SDIM]; s += v; s2 += v * v; }
    } else {
        const float* p = actions + ((size_t)n * BATCH + b0) * ADIM + (f - SDIM);
        #pragma unroll 4
        for (int r = 0; r < RPS; ++r) { float v = p[(size_t)r * ADIM]; s += v; s2 += v * v; }
    }
    atomicAdd(&sum[n * SADIM + f], s);
    atomicAdd(&ssq[n * SADIM + f], s2);
}

__global__ void k_finalize(const float* __restrict__ sum, const float* __restrict__ ssq,
                           float* __restrict__ mean, float* __restrict__ istd) {
    int i = blockIdx.x * blockDim.x + threadIdx.x;
    if (i >= NAG * SADIM) return;
    float m = sum[i] * (1.f / BATCH);
    float v = ssq[i] * (1.f / BATCH) - m * m;
    mean[i] = m;
    istd[i] = rsqrtf(v + 1e-5f);
}

// WcombT[n][j][i] (j=out col 0..511, i=k 0..575), BN-folded, tf32-rounded
__global__ void k_prep_wcombT(const float* __restrict__ Wenc, const float* __restrict__ Ws,
                              const float* __restrict__ istd, float* __restrict__ WT) {
    size_t idx = (size_t)blockIdx.x * blockDim.x + threadIdx.x;
    if (idx >= (size_t)NAG * 512 * SADIM) return;
    int i = (int)(idx % SADIM);
    int j = (int)((idx / SADIM) % 512);
    int n = (int)(idx / (512 * SADIM));
    float is = istd[n * SADIM + i];
    float v;
    if (j < HDIM) v = Wenc[((size_t)n * SADIM + i) * HDIM + j] * is;
    else          v = (i < SDIM) ? Ws[((size_t)n * SDIM + i) * HDIM + (j - HDIM)] * is : 0.f;
    WT[idx] = roundtf(v);
}

__global__ void k_biasfold(const float* __restrict__ benc, const float* __restrict__ bs,
                           const float* __restrict__ Wenc, const float* __restrict__ Ws,
                           const float* __restrict__ mean, const float* __restrict__ istd,
                           float* __restrict__ bcomb) {
    int idx = blockIdx.x * blockDim.x + threadIdx.x;
    if (idx >= NAG * 512) return;
    int n = idx / 512, j = idx % 512;
    float acc;
    if (j < HDIM) {
        acc = benc[n * HDIM + j];
        for (int i = 0; i < SADIM; ++i)
            acc -= mean[n * SADIM + i] * istd[n * SADIM + i] *
                   Wenc[((size_t)n * SADIM + i) * HDIM + j];
    } else {
        int jj = j - HDIM;
        acc = bs[n * HDIM + jj];
        for (int i = 0; i < SDIM; ++i)
            acc -= mean[n * SADIM + i] * istd[n * SADIM + i] *
                   Ws[((size_t)n * SDIM + i) * HDIM + jj];
    }
    bcomb[idx] = acc;
}

// WkvT[j][h] (512 x 256): j<256 -> Wk head cols, else Wv. WselT[j][h] (256 x 256).
__global__ void k_prep_projT(const float* __restrict__ Wk, const float* __restrict__ Wv,
                             const float* __restrict__ Wsel,
                             float* __restrict__ WkvT, float* __restrict__ WselT) {
    int idx = blockIdx.x * blockDim.x + threadIdx.x;
    if (idx < 512 * 256) {
        int j = idx / 256, h = idx % 256;
        int jj = (j < 256) ? j : j - 256;
        int e = jj >> 4, d = jj & 15;
        const float* src = (j < 256) ? Wk : Wv;
        WkvT[idx] = roundtf(src[((size_t)e * HDIM + h) * 16 + d]);
    } else if (idx < 512 * 256 + 256 * 256) {
        int t = idx - 512 * 256;
        int j = t / 256, h = t % 256;
        int e = j >> 4, d = j & 15;
        WselT[t] = roundtf(Wsel[((size_t)e * HDIM + h) * 16 + d]);
    }
}

// Wc1pT[n][j][k] = Wc1[n][sk][j], sk = k<256 ? k+256 : k-256
__global__ void k_prep_wc1pT(const float* __restrict__ Wc1, float* __restrict__ WT) {
    size_t idx = (size_t)blockIdx.x * blockDim.x + threadIdx.x;
    if (idx >= (size_t)NAG * 256 * 512) return;
    int k = (int)(idx % 512);
    int j = (int)((idx / 512) % 256);
    int n = (int)(idx / (512 * 256));
    int sk = (k < 256) ? (k + 256) : (k - 256);
    WT[idx] = roundtf(Wc1[((size_t)n * 512 + sk) * 256 + j]);
}

// ---------------------------------------------------------------------------
// mma.sync tf32 GEMM, 4-stage cp.async pipeline.
// 128x128 block tile, 256 threads (8 warps = 2M x 4N), warp tile 64x32.
// A & B smem tiles: [row][k] pitch 20 floats (80B, 16B-aligned, conflict-free).
// Data is pre-rounded to tf32 in memory -> cp.async streams raw bytes.
// ---------------------------------------------------------------------------
#define NSTAGE 4
#define APITCH 20
#define STAGEF (128 * APITCH)                 // floats per tile per stage
#define GSMEM_BYTES (2 * NSTAGE * STAGEF * 4) // 81920

__global__ void __launch_bounds__(256)
k_gemm_tc(const float* __restrict__ A, int lda, int aoff,
          const float* __restrict__ A2, int lda2, int ksplit,
          const float* __restrict__ WT, size_t w_astride, int ldwt,
          const float* __restrict__ bias, int bias_astride, int special_col0,
          float* __restrict__ C, int ldc, int coff, int K, int round_out)
{
    extern __shared__ float sm[];
    float* AsF = sm;
    float* BsF = sm + NSTAGE * STAGEF;
    const uint32_t sA = smem_u32(AsF);
    const uint32_t sB = smem_u32(BsF);

    const int tid  = threadIdx.x;
    const int lane = tid & 31;
    const int wid  = tid >> 5;
    const int warpM = wid & 1;
    const int warpN = wid >> 1;
    const int lq = lane >> 2;
    const int lr = lane & 3;

    const int n0 = blockIdx.x * 128;
    const int r0 = blockIdx.y * 128;
    const int agent = r0 >> 15;
    const float* Wg = WT + (size_t)agent * w_astride + (size_t)n0 * ldwt;

    // cp.async mapping: each thread copies 2 16B chunks of A and 2 of B.
    const int crow = tid >> 1;          // 0..127
    const int ckq  = (tid & 1) * 2;     // chunk col base {0,2} (chunks of 4 floats)

    float acc[4][4][4];
    #pragma unroll
    for (int mt = 0; mt < 4; ++mt)
        #pragma unroll
        for (int nt = 0; nt < 4; ++nt)
            #pragma unroll
            for (int i = 0; i < 4; ++i) acc[mt][nt][i] = 0.f;

    const int nk = K >> 4;

    auto issue = [&](int s) {
        int buf = s & (NSTAGE - 1);
        int kb = s << 4;
        const float* asrc;
        if (kb < ksplit) asrc = A  + (size_t)(r0 + crow) * lda  + aoff + kb;
        else             asrc = A2 + (size_t)(r0 + crow) * lda2 + (kb - ksplit);
        uint32_t ab = sA + (uint32_t)(buf * STAGEF + crow * APITCH) * 4;
        cp_async16(ab + ckq * 16,        asrc + ckq * 4);
        cp_async16(ab + (ckq + 1) * 16,  asrc + (ckq + 1) * 4);
        const float* bsrc = Wg + (size_t)crow * ldwt + kb;
        uint32_t bb = sB + (uint32_t)(buf * STAGEF + crow * APITCH) * 4;
        cp_async16(bb + ckq * 16,        bsrc + ckq * 4);
        cp_async16(bb + (ckq + 1) * 16,  bsrc + (ckq + 1) * 4);
        cp_commit();
    };

    #pragma unroll
    for (int s = 0; s < NSTAGE - 1; ++s) issue(s);   // nk >= 16 always

    for (int i = 0; i < nk; ++i) {
        cp_wait<NSTAGE - 2>();
        __syncthreads();
        if (i + NSTAGE - 1 < nk) issue(i + NSTAGE - 1);

        const float* as = AsF + (i & (NSTAGE - 1)) * STAGEF;
        const float* bs = BsF + (i & (NSTAGE - 1)) * STAGEF;
        #pragma unroll
        for (int k0 = 0; k0 < 16; k0 += 8) {
            unsigned af[4][4], bf[4][2];
            #pragma unroll
            for (int mt = 0; mt < 4; ++mt) {
                int r = warpM * 64 + mt * 16 + lq;
                af[mt][0] = __float_as_uint(as[r * APITCH + k0 + lr]);
                af[mt][1] = __float_as_uint(as[(r + 8) * APITCH + k0 + lr]);
                af[mt][2] = __float_as_uint(as[r * APITCH + k0 + lr + 4]);
                af[mt][3] = __float_as_uint(as[(r + 8) * APITCH + k0 + lr + 4]);
            }
            #pragma unroll
            for (int nt = 0; nt < 4; ++nt) {
                int nn = warpN * 32 + nt * 8 + lq;
                bf[nt][0] = __float_as_uint(bs[nn * APITCH + k0 + lr]);
                bf[nt][1] = __float_as_uint(bs[nn * APITCH + k0 + lr + 4]);
            }
            #pragma unroll
            for (int mt = 0; mt < 4; ++mt)
                #pragma unroll
                for (int nt = 0; nt < 4; ++nt)
                    mma_tf32(acc[mt][nt], af[mt], bf[nt]);
        }
    }

    // epilogue: bias + leaky-relu on cols >= special_col0, optional tf32 round
    #pragma unroll
    for (int mt = 0; mt < 4; ++mt) {
        int r = r0 + warpM * 64 + mt * 16 + lq;
        #pragma unroll
        for (int nt = 0; nt < 4; ++nt) {
            int gc = blockIdx.x * 128 + warpN * 32 + nt * 8 + 2 * lr;
            float v0 = acc[mt][nt][0], v1 = acc[mt][nt][1];
            float v2 = acc[mt][nt][2], v3 = acc[mt][nt][3];
            if (gc >= special_col0) {
                float b0 = bias[(size_t)agent * bias_astride + (gc     - special_col0)];
                float b1 = bias[(size_t)agent * bias_astride + (gc + 1 - special_col0)];
                v0 += b0; v1 += b1; v2 += b0; v3 += b1;
                v0 = v0 > 0.f ? v0 : 0.01f * v0;
                v1 = v1 > 0.f ? v1 : 0.01f * v1;
                v2 = v2 > 0.f ? v2 : 0.01f * v2;
                v3 = v3 > 0.f ? v3 : 0.01f * v3;
            }
            if (round_out) {
                v0 = roundtf(v0); v1 = roundtf(v1); v2 = roundtf(v2); v3 = roundtf(v3);
            }
            *(float2*)(C + (size_t)r * ldc + coff + gc)       = make_float2(v0, v1);
            *(float2*)(C + (size_t)(r + 8) * ldc + coff + gc) = make_float2(v2, v3);
        }
    }
}

// ---------------------------------------------------------------------------
// Attention (output tf32-rounded for fc1 consumption)
// ---------------------------------------------------------------------------
__global__ void __launch_bounds__(256)
k_attn(const float* __restrict__ kvs, float* __restrict__ enc) {
    __shared__ float sh[4][4][768];
    int tid = threadIdx.x;
    int b0 = blockIdx.x * 4;
    for (int t = tid; t < 3072; t += 256) {
        int row = t / 192, c4 = t % 192;
        int bl = row >> 2, ag = row & 3;
        float4 v = *(const float4*)(kvs + ((size_t)ag * BATCH + b0 + bl) * 768 + c4 * 4);
        *(float4*)&sh[bl][ag][c4 * 4] = v;
    }
    __syncthreads();

    int bl = tid >> 6, rem = tid & 63, e = rem >> 2, i = rem & 3;
    const float* selp = &sh[bl][i][512 + e * 16];
    float logits[4];
    #pragma unroll
    for (int j = 0; j < 4; ++j) {
        const float* kp = &sh[bl][j][e * 16];
        float acc = 0.f;
        #pragma unroll
        for (int d = 0; d < 16; ++d) acc += selp[d] * kp[d];
        logits[j] = acc * 0.25f;
    }
    logits[i] = -1e9f;
    float mx = fmaxf(fmaxf(logits[0], logits[1]), fmaxf(logits[2], logits[3]));
    float p[4], s = 0.f;
    #pragma unroll
    for (int j = 0; j < 4; ++j) { p[j] = __expf(logits[j] - mx); s += p[j]; }
    float inv = 1.f / s;
    float out[16];
    #pragma unroll
    for (int d = 0; d < 16; ++d) out[d] = 0.f;
    #pragma unroll
    for (int j = 0; j < 4; ++j) {
        float pj = p[j] * inv;
        const float* vp = &sh[bl][j][256 + e * 16];
        #pragma unroll
        for (int d = 0; d < 16; ++d) out[d] += pj * vp[d];
    }
    float* dst = enc + ((size_t)i * BATCH + b0 + bl) * 512 + e * 16;
    #pragma unroll
    for (int d = 0; d < 16; d += 4)
        *(float4*)(dst + d) = make_float4(roundtf(out[d]), roundtf(out[d + 1]),
                                          roundtf(out[d + 2]), roundtf(out[d + 3]));
}

// ---------------------------------------------------------------------------
__global__ void __launch_bounds__(256)
k_fc2(const float* __restrict__ actions, const float* __restrict__ Wc2,
      const float* __restrict__ bc2, const float* __restrict__ H,
      float* __restrict__ out) {
    int row = blockIdx.x * 8 + (threadIdx.x >> 5);
    int lane = threadIdx.x & 31;
    int n = row >> 15;
    const float* arow = actions + (size_t)row * ADIM;
    float bestv = -1e30f; int besti = ADIM;
    for (int c = lane; c < ADIM; c += 32) {
        float v = arow[c];
        if (v > bestv || (v == bestv && c < besti)) { bestv = v; besti = c; }
    }
    #pragma unroll
    for (int off = 16; off; off >>= 1) {
        float ov = __shfl_down_sync(0xffffffffu, bestv, off);
        int   oi = __shfl_down_sync(0xffffffffu, besti, off);
        if (ov > bestv || (ov == bestv && oi < besti)) { bestv = ov; besti = oi; }
    }
    besti = __shfl_sync(0xffffffffu, besti, 0);

    const float* hrow = H + (size_t)row * HDIM;
    const float* wcol = Wc2 + (size_t)n * HDIM * ADIM + besti;
    float acc = 0.f;
    for (int k = lane; k < HDIM; k += 32)
        acc += hrow[k] * wcol[(size_t)k * ADIM];
    #pragma unroll
    for (int off = 16; off; off >>= 1)
        acc += __shfl_down_sync(0xffffffffu, acc, off);
    if (lane == 0) out[row] = acc + bc2[n * ADIM + besti];
}

// ---------------------------------------------------------------------------
extern "C" void kernel_launch(void* const* d_in, const int* in_sizes, int n_in,
                              void* d_out, int out_size) {
    (void)in_sizes; (void)n_in; (void)out_size;
    const float* states  = (const float*)d_in[0];
    const float* actions = (const float*)d_in[1];
    const float* Wenc    = (const float*)d_in[2];
    const float* benc    = (const float*)d_in[3];
    const float* Ws      = (const float*)d_in[4];
    const float* bs      = (const float*)d_in[5];
    const float* Wk      = (const float*)d_in[6];
    const float* Wsel    = (const float*)d_in[7];
    const float* Wv      = (const float*)d_in[8];
    const float* bv      = (const float*)d_in[9];
    const float* Wc1     = (const float*)d_in[10];
    const float* bc1     = (const float*)d_in[11];
    const float* Wc2     = (const float*)d_in[12];
    const float* bc2     = (const float*)d_in[13];
    float* out = (float*)d_out;

    float* S = nullptr;
    cudaGetSymbolAddress((void**)&S, g_scratch);
    float* SUM    = S + O_SUM;
    float* SSQ    = S + O_SSQ;
    float* MEAN   = S + O_MEAN;
    float* ISTD   = S + O_ISTD;
    float* BCOMB  = S + O_BCOMB;
    float* WCOMBT = S + O_WCOMBT;
    float* WKVT   = S + O_WKVT;
    float* WSELT  = S + O_WSELT;
    float* WC1PT  = S + O_WC1PT;
    float* ENC    = S + O_ENC;
    float* KVS    = S + O_KVS;
    float* HBUF   = S + O_H;
    float* STF    = S + O_STF;
    float* ATF    = S + O_ATF;

    const int BIG = 1 << 30;

    static bool attr_done = false;
    if (!attr_done) {
        cudaFuncSetAttribute(k_gemm_tc, cudaFuncAttributeMaxDynamicSharedMemorySize,
                             GSMEM_BYTES);
        attr_done = true;
    }

    // 1) batch stats + tf32-rounded input copies
    k_zero<<<(4608 + 255) / 256, 256>>>(SUM, 4608);
    k_stats<<<dim3(4, 64), 576>>>(states, actions, SUM, SSQ);
    k_finalize<<<(2304 + 255) / 256, 256>>>(SUM, SSQ, MEAN, ISTD);
    k_round4<<<(int)(((size_t)ROWS * SDIM / 4 + 255) / 256), 256>>>(states, STF, (size_t)ROWS * SDIM);
    k_round4<<<(int)(((size_t)ROWS * ADIM / 4 + 255) / 256), 256>>>(actions, ATF, (size_t)ROWS * ADIM);

    // 2) weight prep (BN fold + transpose + tf32 rounding)
    k_prep_wcombT<<<(int)(((size_t)NAG * 512 * SADIM + 255) / 256), 256>>>(Wenc, Ws, ISTD, WCOMBT);
    k_biasfold<<<(NAG * 512 + 255) / 256, 256>>>(benc, bs, Wenc, Ws, MEAN, ISTD, BCOMB);
    k_prep_projT<<<(512 * 256 + 256 * 256 + 255) / 256, 256>>>(Wk, Wv, Wsel, WKVT, WSELT);
    k_prep_wc1pT<<<(int)(((size_t)NAG * 256 * 512 + 255) / 256), 256>>>(Wc1, WC1PT);

    // 3) encoder GEMM: [STF|ATF] (K=576) -> ENC [sa_enc|s_enc] (N=512), rounded
    k_gemm_tc<<<dim3(4, ROWS / 128), 256, GSMEM_BYTES>>>(
        STF, SDIM, 0, ATF, ADIM, SDIM,
        WCOMBT, (size_t)512 * SADIM, SADIM,
        BCOMB, 512, 0,
        ENC, 512, 0, SADIM, 1);
    // 4) keys|vals: sa_enc (K=256) -> KVS cols 0..511 (vals bias+lrelu), rounded
    k_gemm_tc<<<dim3(4, ROWS / 128), 256, GSMEM_BYTES>>>(
        ENC, 512, 0, ENC, 512, BIG,
        WKVT, 0, 256,
        bv, 0, 256,
        KVS, 768, 0, 256, 1);
    //    sel: s_enc (K=256) -> KVS cols 512..767, rounded
    k_gemm_tc<<<dim3(2, ROWS / 128), 256, GSMEM_BYTES>>>(
        ENC, 512, 256, ENC, 512, BIG,
        WSELT, 0, 256,
        bv, 0, BIG,
        KVS, 768, 512, 256, 1);
    // 5) attention -> other (rounded) into ENC cols 0..255
    k_attn<<<BATCH / 4, 256>>>(KVS, ENC);
    // 6) critic fc1: ENC (K=512) @ Wc1pT -> H (bc1 + lrelu, fp32 out)
    k_gemm_tc<<<dim3(2, ROWS / 128), 256, GSMEM_BYTES>>>(
        ENC, 512, 0, ENC, 512, BIG,
        WC1PT, (size_t)256 * 512, 512,
        bc1, 256, 0,
        HBUF, 256, 0, 512, 0);
    // 7) fc2 + argmax gather
    k_fc2<<<ROWS / 8, 256>>>(actions, Wc2, bc2, HBUF, out);
}

// round 6
// speedup vs baseline: 3.9658x; 1.5955x over previous
#include <cuda_runtime.h>
#include <cuda_fp16.h>
#include <cstdint>

// ---------------------------------------------------------------------------
// AttentionCritic: N=4 agents, B=32768, S=512, A=64, H=256, NH=16, D=16
// Round 6: R5 (fp16 mma.sync m16n8k16, half storage, 4-stage cp.async)
// with the scratch-layout OOB fixed (STH slot count was under-reserved 2x).
// ---------------------------------------------------------------------------

#define NAG   4
#define BATCH 32768
#define ROWS  (NAG * BATCH)       // 131072
#define SDIM  512
#define ADIM  64
#define SADIM 576
#define HDIM  256

// ---- scratch layout (float slots; half arrays use 2 halves per slot) ----
constexpr size_t O_SUM    = 0;
constexpr size_t O_SSQ    = 2304;
constexpr size_t O_MEAN   = 4608;
constexpr size_t O_ISTD   = 6912;
constexpr size_t O_BCOMB  = 9216;           // 2048 floats
constexpr size_t O_WCOMBT = 11264;          // 4*512*576 halves  = 589824 slots
constexpr size_t O_WKVT   = 601088;         // 512*256 halves    = 65536 slots
constexpr size_t O_WSELT  = 666624;         // 256*256 halves    = 32768 slots
constexpr size_t O_WC1PT  = 699392;         // 4*256*512 halves  = 262144 slots
constexpr size_t O_ENC    = 961536;         // 131072*512 halves = 33554432 slots
constexpr size_t O_KVS    = 34515968;       // 131072*768 halves = 50331648 slots
constexpr size_t O_H      = 84847616;       // 131072*256 floats = 33554432 slots
constexpr size_t O_STH    = 118402048;      // 131072*512 halves = 33554432 slots
constexpr size_t O_ATH    = 151956480;      // 131072*64 halves  = 4194304 slots
constexpr size_t SCRATCH_FLOATS = 156150784;

__device__ float g_scratch[SCRATCH_FLOATS];

// ---------------------------------------------------------------------------
__device__ __forceinline__ void mma_f16(float* d, const unsigned* a, const unsigned* b) {
    asm("mma.sync.aligned.m16n8k16.row.col.f32.f16.f16.f32 "
        "{%0,%1,%2,%3}, {%4,%5,%6,%7}, {%8,%9}, {%0,%1,%2,%3};"
        : "+f"(d[0]), "+f"(d[1]), "+f"(d[2]), "+f"(d[3])
        : "r"(a[0]), "r"(a[1]), "r"(a[2]), "r"(a[3]), "r"(b[0]), "r"(b[1]));
}
__device__ __forceinline__ uint32_t smem_u32(const void* p) {
    uint32_t a;
    asm("{ .reg .u64 t; cvta.to.shared.u64 t, %1; cvt.u32.u64 %0, t; }" : "=r"(a) : "l"(p));
    return a;
}
__device__ __forceinline__ void cp_async16(uint32_t dst, const void* src) {
    asm volatile("cp.async.cg.shared.global [%0], [%1], 16;" :: "r"(dst), "l"(src) : "memory");
}
__device__ __forceinline__ void cp_commit() {
    asm volatile("cp.async.commit_group;" ::: "memory");
}
template <int N>
__device__ __forceinline__ void cp_wait() {
    asm volatile("cp.async.wait_group %0;" :: "n"(N) : "memory");
}
__device__ __forceinline__ uint32_t h2bits(__half2 h) {
    return *reinterpret_cast<uint32_t*>(&h);
}

// ---------------------------------------------------------------------------
__global__ void k_zero(float* p, int n) {
    int i = blockIdx.x * blockDim.x + threadIdx.x;
    if (i < n) p[i] = 0.f;
}

// float -> half convert copy (n multiple of 4)
__global__ void k_tohalf(const float* __restrict__ in, __half* __restrict__ out, size_t n) {
    size_t i = ((size_t)blockIdx.x * blockDim.x + threadIdx.x) * 4;
    if (i >= n) return;
    float4 v = *(const float4*)(in + i);
    __half2 h0 = __floats2half2_rn(v.x, v.y);
    __half2 h1 = __floats2half2_rn(v.z, v.w);
    uint2 u; u.x = h2bits(h0); u.y = h2bits(h1);
    *(uint2*)(out + i) = u;
}

// grid (4, 64), block 576
__global__ void k_stats(const float* __restrict__ states,
                        const float* __restrict__ actions,
                        float* __restrict__ sum, float* __restrict__ ssq) {
    int n = blockIdx.x, slab = blockIdx.y, f = threadIdx.x;
    const int RPS = BATCH / 64;
    int b0 = slab * RPS;
    float s = 0.f, s2 = 0.f;
    if (f < SDIM) {
        const float* p = states + ((size_t)n * BATCH + b0) * SDIM + f;
        #pragma unroll 4
        for (int r = 0; r < RPS; ++r) { float v = p[(size_t)r * SDIM]; s += v; s2 += v * v; }
    } else {
        const float* p = actions + ((size_t)n * BATCH + b0) * ADIM + (f - SDIM);
        #pragma unroll 4
        for (int r = 0; r < RPS; ++r) { float v = p[(size_t)r * ADIM]; s += v; s2 += v * v; }
    }
    atomicAdd(&sum[n * SADIM + f], s);
    atomicAdd(&ssq[n * SADIM + f], s2);
}

__global__ void k_finalize(const float* __restrict__ sum, const float* __restrict__ ssq,
                           float* __restrict__ mean, float* __restrict__ istd) {
    int i = blockIdx.x * blockDim.x + threadIdx.x;
    if (i >= NAG * SADIM) return;
    float m = sum[i] * (1.f / BATCH);
    float v = ssq[i] * (1.f / BATCH) - m * m;
    mean[i] = m;
    istd[i] = rsqrtf(v + 1e-5f);
}

// WcombT[n][j][i] (j=out col 0..511, i=k 0..575), BN-folded, half
__global__ void k_prep_wcombT(const float* __restrict__ Wenc, const float* __restrict__ Ws,
                              const float* __restrict__ istd, __half* __restrict__ WT) {
    size_t idx = (size_t)blockIdx.x * blockDim.x + threadIdx.x;
    if (idx >= (size_t)NAG * 512 * SADIM) return;
    int i = (int)(idx % SADIM);
    int j = (int)((idx / SADIM) % 512);
    int n = (int)(idx / (512 * SADIM));
    float is = istd[n * SADIM + i];
    float v;
    if (j < HDIM) v = Wenc[((size_t)n * SADIM + i) * HDIM + j] * is;
    else          v = (i < SDIM) ? Ws[((size_t)n * SDIM + i) * HDIM + (j - HDIM)] * is : 0.f;
    WT[idx] = __float2half_rn(v);
}

__global__ void k_biasfold(const float* __restrict__ benc, const float* __restrict__ bs,
                           const float* __restrict__ Wenc, const float* __restrict__ Ws,
                           const float* __restrict__ mean, const float* __restrict__ istd,
                           float* __restrict__ bcomb) {
    int idx = blockIdx.x * blockDim.x + threadIdx.x;
    if (idx >= NAG * 512) return;
    int n = idx / 512, j = idx % 512;
    float acc;
    if (j < HDIM) {
        acc = benc[n * HDIM + j];
        for (int i = 0; i < SADIM; ++i)
            acc -= mean[n * SADIM + i] * istd[n * SADIM + i] *
                   Wenc[((size_t)n * SADIM + i) * HDIM + j];
    } else {
        int jj = j - HDIM;
        acc = bs[n * HDIM + jj];
        for (int i = 0; i < SDIM; ++i)
            acc -= mean[n * SADIM + i] * istd[n * SADIM + i] *
                   Ws[((size_t)n * SDIM + i) * HDIM + jj];
    }
    bcomb[idx] = acc;
}

// WkvT[j][h] (512 x 256): j<256 -> Wk head cols, else Wv. WselT[j][h] (256 x 256).
__global__ void k_prep_projT(const float* __restrict__ Wk, const float* __restrict__ Wv,
                             const float* __restrict__ Wsel,
                             __half* __restrict__ WkvT, __half* __restrict__ WselT) {
    int idx = blockIdx.x * blockDim.x + threadIdx.x;
    if (idx < 512 * 256) {
        int j = idx / 256, h = idx % 256;
        int jj = (j < 256) ? j : j - 256;
        int e = jj >> 4, d = jj & 15;
        const float* src = (j < 256) ? Wk : Wv;
        WkvT[idx] = __float2half_rn(src[((size_t)e * HDIM + h) * 16 + d]);
    } else if (idx < 512 * 256 + 256 * 256) {
        int t = idx - 512 * 256;
        int j = t / 256, h = t % 256;
        int e = j >> 4, d = j & 15;
        WselT[t] = __float2half_rn(Wsel[((size_t)e * HDIM + h) * 16 + d]);
    }
}

// Wc1pT[n][j][k] = Wc1[n][sk][j], sk = k<256 ? k+256 : k-256
__global__ void k_prep_wc1pT(const float* __restrict__ Wc1, __half* __restrict__ WT) {
    size_t idx = (size_t)blockIdx.x * blockDim.x + threadIdx.x;
    if (idx >= (size_t)NAG * 256 * 512) return;
    int k = (int)(idx % 512);
    int j = (int)((idx / 512) % 256);
    int n = (int)(idx / (512 * 256));
    int sk = (k < 256) ? (k + 256) : (k - 256);
    WT[idx] = __float2half_rn(Wc1[((size_t)n * 512 + sk) * 256 + j]);
}

// ---------------------------------------------------------------------------
// fp16 mma.sync GEMM, 4-stage cp.async pipeline.
// 128x128 block tile, 256 threads (8 warps = 2M x 4N), warp tile 64x32,
// K staged 32 halves (64B/row). Smem rows pitch 40 halves (80B) ->
// conflict-free 32-bit fragment loads. Output: half (Ch) or float (Cf).
// ---------------------------------------------------------------------------
#define NSTAGE 4
#define HPITCH 40
#define STAGEH (128 * HPITCH)            // halves per tile-stage
#define STAGEB (STAGEH * 2)              // 10240 bytes
#define GSMEM_BYTES (2 * NSTAGE * STAGEB) // 81920

__global__ void __launch_bounds__(256)
k_gemm_h(const __half* __restrict__ A, int lda, int aoff,
         const __half* __restrict__ A2, int lda2, int ksplit,
         const __half* __restrict__ WT, size_t w_astride, int ldwt,
         const float* __restrict__ bias, int bias_astride, int special_col0,
         __half* __restrict__ Ch, float* __restrict__ Cf,
         int ldc, int coff, int K)
{
    extern __shared__ __half smh[];
    __half* Ash = smh;
    __half* Bsh = smh + NSTAGE * STAGEH;
    const uint32_t sA = smem_u32(Ash);
    const uint32_t sB = smem_u32(Bsh);

    const int tid  = threadIdx.x;
    const int lane = tid & 31;
    const int wid  = tid >> 5;
    const int warpM = wid & 1;
    const int warpN = wid >> 1;
    const int lq = lane >> 2;
    const int lr = lane & 3;

    const int n0 = blockIdx.x * 128;
    const int r0 = blockIdx.y * 128;
    const int agent = r0 >> 15;
    const __half* Wg = WT + (size_t)agent * w_astride + (size_t)n0 * ldwt;

    const int crow = tid >> 1;          // 0..127
    const int ckq  = (tid & 1) * 2;     // 16B-chunk base {0,2} of 4 per row

    float acc[4][4][4];
    #pragma unroll
    for (int mt = 0; mt < 4; ++mt)
        #pragma unroll
        for (int nt = 0; nt < 4; ++nt)
            #pragma unroll
            for (int i = 0; i < 4; ++i) acc[mt][nt][i] = 0.f;

    const int nk = K >> 5;

    auto issue = [&](int s) {
        int buf = s & (NSTAGE - 1);
        int kb = s << 5;
        const __half* asrc;
        if (kb < ksplit) asrc = A  + (size_t)(r0 + crow) * lda  + aoff + kb;
        else             asrc = A2 + (size_t)(r0 + crow) * lda2 + (kb - ksplit);
        uint32_t ab = sA + (uint32_t)(buf * STAGEB + crow * (HPITCH * 2));
        cp_async16(ab + ckq * 16,       asrc + ckq * 8);
        cp_async16(ab + (ckq + 1) * 16, asrc + (ckq + 1) * 8);
        const __half* bsrc = Wg + (size_t)crow * ldwt + kb;
        uint32_t bb = sB + (uint32_t)(buf * STAGEB + crow * (HPITCH * 2));
        cp_async16(bb + ckq * 16,       bsrc + ckq * 8);
        cp_async16(bb + (ckq + 1) * 16, bsrc + (ckq + 1) * 8);
        cp_commit();
    };

    #pragma unroll
    for (int s = 0; s < NSTAGE - 1; ++s) issue(s);   // nk >= 8 always

    for (int i = 0; i < nk; ++i) {
        cp_wait<NSTAGE - 2>();
        __syncthreads();
        if (i + NSTAGE - 1 < nk) issue(i + NSTAGE - 1);

        const __half* as = Ash + (i & (NSTAGE - 1)) * STAGEH;
        const __half* bs = Bsh + (i & (NSTAGE - 1)) * STAGEH;
        #pragma unroll
        for (int k0 = 0; k0 < 32; k0 += 16) {
            unsigned af[4][4], bf[4][2];
            #pragma unroll
            for (int mt = 0; mt < 4; ++mt) {
                int r = warpM * 64 + mt * 16 + lq;
                af[mt][0] = *(const uint32_t*)&as[r * HPITCH + k0 + 2 * lr];
                af[mt][1] = *(const uint32_t*)&as[(r + 8) * HPITCH + k0 + 2 * lr];
                af[mt][2] = *(const uint32_t*)&as[r * HPITCH + k0 + 2 * lr + 8];
                af[mt][3] = *(const uint32_t*)&as[(r + 8) * HPITCH + k0 + 2 * lr + 8];
            }
            #pragma unroll
            for (int nt = 0; nt < 4; ++nt) {
                int nn = warpN * 32 + nt * 8 + lq;
                bf[nt][0] = *(const uint32_t*)&bs[nn * HPITCH + k0 + 2 * lr];
                bf[nt][1] = *(const uint32_t*)&bs[nn * HPITCH + k0 + 2 * lr + 8];
            }
            #pragma unroll
            for (int mt = 0; mt < 4; ++mt)
                #pragma unroll
                for (int nt = 0; nt < 4; ++nt)
                    mma_f16(acc[mt][nt], af[mt], bf[nt]);
        }
    }

    // epilogue: bias + leaky-relu on cols >= special_col0; half or float store
    #pragma unroll
    for (int mt = 0; mt < 4; ++mt) {
        int r = r0 + warpM * 64 + mt * 16 + lq;
        #pragma unroll
        for (int nt = 0; nt < 4; ++nt) {
            int gc = blockIdx.x * 128 + warpN * 32 + nt * 8 + 2 * lr;
            float v0 = acc[mt][nt][0], v1 = acc[mt][nt][1];
            float v2 = acc[mt][nt][2], v3 = acc[mt][nt][3];
            if (gc >= special_col0) {
                float b0 = bias[(size_t)agent * bias_astride + (gc     - special_col0)];
                float b1 = bias[(size_t)agent * bias_astride + (gc + 1 - special_col0)];
                v0 += b0; v1 += b1; v2 += b0; v3 += b1;
                v0 = v0 > 0.f ? v0 : 0.01f * v0;
                v1 = v1 > 0.f ? v1 : 0.01f * v1;
                v2 = v2 > 0.f ? v2 : 0.01f * v2;
                v3 = v3 > 0.f ? v3 : 0.01f * v3;
            }
            if (Ch) {
                *(uint32_t*)(Ch + (size_t)r * ldc + coff + gc) =
                    h2bits(__floats2half2_rn(v0, v1));
                *(uint32_t*)(Ch + (size_t)(r + 8) * ldc + coff + gc) =
                    h2bits(__floats2half2_rn(v2, v3));
            } else {
                *(float2*)(Cf + (size_t)r * ldc + coff + gc)       = make_float2(v0, v1);
                *(float2*)(Cf + (size_t)(r + 8) * ldc + coff + gc) = make_float2(v2, v3);
            }
        }
    }
}

// ---------------------------------------------------------------------------
// Attention: half in (KVS), half out (`other` into ENC cols 0..255)
// ---------------------------------------------------------------------------
__global__ void __launch_bounds__(256)
k_attn(const __half* __restrict__ kvs, __half* __restrict__ enc) {
    __shared__ float sh[4][4][768];    // 48KB
    int tid = threadIdx.x;
    int b0 = blockIdx.x * 4;
    for (int t = tid; t < 1536; t += 256) {
        int row = t / 96, c8 = t % 96;
        int bl = row >> 2, ag = row & 3;
        uint4 v = *(const uint4*)(kvs + ((size_t)ag * BATCH + b0 + bl) * 768 + c8 * 8);
        const __half2* hp = (const __half2*)&v;
        float* dst = &sh[bl][ag][c8 * 8];
        #pragma unroll
        for (int j = 0; j < 4; ++j) {
            float2 f = __half22float2(hp[j]);
            dst[2 * j] = f.x; dst[2 * j + 1] = f.y;
        }
    }
    __syncthreads();

    int bl = tid >> 6, rem = tid & 63, e = rem >> 2, i = rem & 3;
    const float* selp = &sh[bl][i][512 + e * 16];
    float logits[4];
    #pragma unroll
    for (int j = 0; j < 4; ++j) {
        const float* kp = &sh[bl][j][e * 16];
        float acc = 0.f;
        #pragma unroll
        for (int d = 0; d < 16; ++d) acc += selp[d] * kp[d];
        logits[j] = acc * 0.25f;
    }
    logits[i] = -1e9f;
    float mx = fmaxf(fmaxf(logits[0], logits[1]), fmaxf(logits[2], logits[3]));
    float p[4], s = 0.f;
    #pragma unroll
    for (int j = 0; j < 4; ++j) { p[j] = __expf(logits[j] - mx); s += p[j]; }
    float inv = 1.f / s;
    float out[16];
    #pragma unroll
    for (int d = 0; d < 16; ++d) out[d] = 0.f;
    #pragma unroll
    for (int j = 0; j < 4; ++j) {
        float pj = p[j] * inv;
        const float* vp = &sh[bl][j][256 + e * 16];
        #pragma unroll
        for (int d = 0; d < 16; ++d) out[d] += pj * vp[d];
    }
    __half* dst = enc + ((size_t)i * BATCH + b0 + bl) * 512 + e * 16;
    uint4 o;
    o.x = h2bits(__floats2half2_rn(out[0], out[1]));
    o.y = h2bits(__floats2half2_rn(out[2], out[3]));
    o.z = h2bits(__floats2half2_rn(out[4], out[5]));
    o.w = h2bits(__floats2half2_rn(out[6], out[7]));
    *(uint4*)dst = o;
    o.x = h2bits(__floats2half2_rn(out[8], out[9]));
    o.y = h2bits(__floats2half2_rn(out[10], out[11]));
    o.z = h2bits(__floats2half2_rn(out[12], out[13]));
    o.w = h2bits(__floats2half2_rn(out[14], out[15]));
    *(uint4*)(dst + 8) = o;
}

// ---------------------------------------------------------------------------
__global__ void __launch_bounds__(256)
k_fc2(const float* __restrict__ actions, const float* __restrict__ Wc2,
      const float* __restrict__ bc2, const float* __restrict__ H,
      float* __restrict__ out) {
    int row = blockIdx.x * 8 + (threadIdx.x >> 5);
    int lane = threadIdx.x & 31;
    int n = row >> 15;
    const float* arow = actions + (size_t)row * ADIM;
    float bestv = -1e30f; int besti = ADIM;
    for (int c = lane; c < ADIM; c += 32) {
        float v = arow[c];
        if (v > bestv || (v == bestv && c < besti)) { bestv = v; besti = c; }
    }
    #pragma unroll
    for (int off = 16; off; off >>= 1) {
        float ov = __shfl_down_sync(0xffffffffu, bestv, off);
        int   oi = __shfl_down_sync(0xffffffffu, besti, off);
        if (ov > bestv || (ov == bestv && oi < besti)) { bestv = ov; besti = oi; }
    }
    besti = __shfl_sync(0xffffffffu, besti, 0);

    const float* hrow = H + (size_t)row * HDIM;
    const float* wcol = Wc2 + (size_t)n * HDIM * ADIM + besti;
    float acc = 0.f;
    for (int k = lane; k < HDIM; k += 32)
        acc += hrow[k] * wcol[(size_t)k * ADIM];
    #pragma unroll
    for (int off = 16; off; off >>= 1)
        acc += __shfl_down_sync(0xffffffffu, acc, off);
    if (lane == 0) out[row] = acc + bc2[n * ADIM + besti];
}

// ---------------------------------------------------------------------------
extern "C" void kernel_launch(void* const* d_in, const int* in_sizes, int n_in,
                              void* d_out, int out_size) {
    (void)in_sizes; (void)n_in; (void)out_size;
    const float* states  = (const float*)d_in[0];
    const float* actions = (const float*)d_in[1];
    const float* Wenc    = (const float*)d_in[2];
    const float* benc    = (const float*)d_in[3];
    const float* Ws      = (const float*)d_in[4];
    const float* bs      = (const float*)d_in[5];
    const float* Wk      = (const float*)d_in[6];
    const float* Wsel    = (const float*)d_in[7];
    const float* Wv      = (const float*)d_in[8];
    const float* bv      = (const float*)d_in[9];
    const float* Wc1     = (const float*)d_in[10];
    const float* bc1     = (const float*)d_in[11];
    const float* Wc2     = (const float*)d_in[12];
    const float* bc2     = (const float*)d_in[13];
    float* out = (float*)d_out;

    float* S = nullptr;
    cudaGetSymbolAddress((void**)&S, g_scratch);
    float* SUM    = S + O_SUM;
    float* SSQ    = S + O_SSQ;
    float* MEAN   = S + O_MEAN;
    float* ISTD   = S + O_ISTD;
    float* BCOMB  = S + O_BCOMB;
    __half* WCOMBTh = (__half*)(S + O_WCOMBT);
    __half* WKVTh   = (__half*)(S + O_WKVT);
    __half* WSELTh  = (__half*)(S + O_WSELT);
    __half* WC1PTh  = (__half*)(S + O_WC1PT);
    __half* ENCh    = (__half*)(S + O_ENC);
    __half* KVSh    = (__half*)(S + O_KVS);
    float*  HBUF    = S + O_H;
    __half* STH     = (__half*)(S + O_STH);
    __half* ATH     = (__half*)(S + O_ATH);

    const int BIG = 1 << 30;

    cudaFuncSetAttribute(k_gemm_h, cudaFuncAttributeMaxDynamicSharedMemorySize, GSMEM_BYTES);

    // 1) batch stats + half input copies
    k_zero<<<(4608 + 255) / 256, 256>>>(SUM, 4608);
    k_stats<<<dim3(4, 64), 576>>>(states, actions, SUM, SSQ);
    k_finalize<<<(2304 + 255) / 256, 256>>>(SUM, SSQ, MEAN, ISTD);
    k_tohalf<<<(int)(((size_t)ROWS * SDIM / 4 + 255) / 256), 256>>>(states, STH, (size_t)ROWS * SDIM);
    k_tohalf<<<(int)(((size_t)ROWS * ADIM / 4 + 255) / 256), 256>>>(actions, ATH, (size_t)ROWS * ADIM);

    // 2) weight prep (BN fold + transpose + half)
    k_prep_wcombT<<<(int)(((size_t)NAG * 512 * SADIM + 255) / 256), 256>>>(Wenc, Ws, ISTD, WCOMBTh);
    k_biasfold<<<(NAG * 512 + 255) / 256, 256>>>(benc, bs, Wenc, Ws, MEAN, ISTD, BCOMB);
    k_prep_projT<<<(512 * 256 + 256 * 256 + 255) / 256, 256>>>(Wk, Wv, Wsel, WKVTh, WSELTh);
    k_prep_wc1pT<<<(int)(((size_t)NAG * 256 * 512 + 255) / 256), 256>>>(Wc1, WC1PTh);

    // 3) encoder GEMM: [STH|ATH] (K=576) -> ENC [sa_enc|s_enc] (half)
    k_gemm_h<<<dim3(4, ROWS / 128), 256, GSMEM_BYTES>>>(
        STH, SDIM, 0, ATH, ADIM, SDIM,
        WCOMBTh, (size_t)512 * SADIM, SADIM,
        BCOMB, 512, 0,
        ENCh, nullptr, 512, 0, SADIM);
    // 4) keys|vals: sa_enc (K=256) -> KVS cols 0..511 (vals bias+lrelu)
    k_gemm_h<<<dim3(4, ROWS / 128), 256, GSMEM_BYTES>>>(
        ENCh, 512, 0, ENCh, 512, BIG,
        WKVTh, 0, 256,
        bv, 0, 256,
        KVSh, nullptr, 768, 0, 256);
    //    sel: s_enc (K=256) -> KVS cols 512..767
    k_gemm_h<<<dim3(2, ROWS / 128), 256, GSMEM_BYTES>>>(
        ENCh, 512, 256, ENCh, 512, BIG,
        WSELTh, 0, 256,
        bv, 0, BIG,
        KVSh, nullptr, 768, 512, 256);
    // 5) attention -> other (half) into ENC cols 0..255
    k_attn<<<BATCH / 4, 256>>>(KVSh, ENCh);
    // 6) critic fc1: ENC (K=512) @ Wc1pT -> H (bc1 + lrelu, fp32 out)
    k_gemm_h<<<dim3(2, ROWS / 128), 256, GSMEM_BYTES>>>(
        ENCh, 512, 0, ENCh, 512, BIG,
        WC1PTh, (size_t)256 * 512, 512,
        bc1, 256, 0,
        nullptr, HBUF, 256, 0, 512);
    // 7) fc2 + argmax gather
    k_fc2<<<ROWS / 8, 256>>>(actions, Wc2, bc2, HBUF, out);
}

// round 8
// speedup vs baseline: 4.4069x; 1.1112x over previous
#include <cuda_runtime.h>
#include <cuda_fp16.h>
#include <cstdint>

// ---------------------------------------------------------------------------
// AttentionCritic: N=4 agents, B=32768, S=512, A=64, H=256, NH=16, D=16
// Round 8: R7 resubmitted verbatim (R7 bench was an infra failure --
// "GB300 container failed twice" -- the kernel never ran).
// R7 = R6 + ldmatrix fragment loads, tohalf fused into stats,
// kv+sel merged into one GEMM launch, H stored half.
// ---------------------------------------------------------------------------

#define NAG   4
#define BATCH 32768
#define ROWS  (NAG * BATCH)       // 131072
#define SDIM  512
#define ADIM  64
#define SADIM 576
#define HDIM  256

// ---- scratch layout (float slots; half arrays use 2 halves per slot) ----
constexpr size_t O_SUM    = 0;
constexpr size_t O_SSQ    = 2304;
constexpr size_t O_MEAN   = 4608;
constexpr size_t O_ISTD   = 6912;
constexpr size_t O_BCOMB  = 9216;           // 2048 floats
constexpr size_t O_WCOMBT = 11264;          // 4*512*576 halves  = 589824 slots
constexpr size_t O_WKVT   = 601088;         // 512*256 halves    = 65536 slots (sel follows contiguously)
constexpr size_t O_WSELT  = 666624;         // 256*256 halves    = 32768 slots
constexpr size_t O_WC1PT  = 699392;         // 4*256*512 halves  = 262144 slots
constexpr size_t O_ENC    = 961536;         // 131072*512 halves = 33554432 slots
constexpr size_t O_KVS    = 34515968;       // 131072*768 halves = 50331648 slots
constexpr size_t O_H      = 84847616;       // 131072*256 halves = 16777216 slots
constexpr size_t O_STH    = 118402048;      // 131072*512 halves = 33554432 slots
constexpr size_t O_ATH    = 151956480;      // 131072*64 halves  = 4194304 slots
constexpr size_t SCRATCH_FLOATS = 156150784;

__device__ float g_scratch[SCRATCH_FLOATS];

// ---------------------------------------------------------------------------
__device__ __forceinline__ void mma_f16(float* d, const unsigned* a, const unsigned* b) {
    asm("mma.sync.aligned.m16n8k16.row.col.f32.f16.f16.f32 "
        "{%0,%1,%2,%3}, {%4,%5,%6,%7}, {%8,%9}, {%0,%1,%2,%3};"
        : "+f"(d[0]), "+f"(d[1]), "+f"(d[2]), "+f"(d[3])
        : "r"(a[0]), "r"(a[1]), "r"(a[2]), "r"(a[3]), "r"(b[0]), "r"(b[1]));
}
__device__ __forceinline__ void ldsm_x4(unsigned* r, uint32_t addr) {
    asm volatile("ldmatrix.sync.aligned.m8n8.x4.shared.b16 {%0,%1,%2,%3}, [%4];"
                 : "=r"(r[0]), "=r"(r[1]), "=r"(r[2]), "=r"(r[3]) : "r"(addr));
}
__device__ __forceinline__ void ldsm_x2(unsigned* r, uint32_t addr) {
    asm volatile("ldmatrix.sync.aligned.m8n8.x2.shared.b16 {%0,%1}, [%2];"
                 : "=r"(r[0]), "=r"(r[1]) : "r"(addr));
}
__device__ __forceinline__ uint32_t smem_u32(const void* p) {
    uint32_t a;
    asm("{ .reg .u64 t; cvta.to.shared.u64 t, %1; cvt.u32.u64 %0, t; }" : "=r"(a) : "l"(p));
    return a;
}
__device__ __forceinline__ void cp_async16(uint32_t dst, const void* src) {
    asm volatile("cp.async.cg.shared.global [%0], [%1], 16;" :: "r"(dst), "l"(src) : "memory");
}
__device__ __forceinline__ void cp_commit() {
    asm volatile("cp.async.commit_group;" ::: "memory");
}
template <int N>
__device__ __forceinline__ void cp_wait() {
    asm volatile("cp.async.wait_group %0;" :: "n"(N) : "memory");
}
__device__ __forceinline__ uint32_t h2bits(__half2 h) {
    return *reinterpret_cast<uint32_t*>(&h);
}

// ---------------------------------------------------------------------------
__global__ void k_zero(float* p, int n) {
    int i = blockIdx.x * blockDim.x + threadIdx.x;
    if (i < n) p[i] = 0.f;
}

// grid (4, 64), block 576. Also writes half copies of states/actions.
__global__ void k_stats(const float* __restrict__ states,
                        const float* __restrict__ actions,
                        float* __restrict__ sum, float* __restrict__ ssq,
                        __half* __restrict__ sth, __half* __restrict__ ath) {
    int n = blockIdx.x, slab = blockIdx.y, f = threadIdx.x;
    const int RPS = BATCH / 64;
    int b0 = slab * RPS;
    float s = 0.f, s2 = 0.f;
    if (f < SDIM) {
        const float* p = states + ((size_t)n * BATCH + b0) * SDIM + f;
        __half* q = sth + ((size_t)n * BATCH + b0) * SDIM + f;
        #pragma unroll 4
        for (int r = 0; r < RPS; ++r) {
            float v = p[(size_t)r * SDIM];
            s += v; s2 += v * v;
            q[(size_t)r * SDIM] = __float2half_rn(v);
        }
    } else {
        const float* p = actions + ((size_t)n * BATCH + b0) * ADIM + (f - SDIM);
        __half* q = ath + ((size_t)n * BATCH + b0) * ADIM + (f - SDIM);
        #pragma unroll 4
        for (int r = 0; r < RPS; ++r) {
            float v = p[(size_t)r * ADIM];
            s += v; s2 += v * v;
            q[(size_t)r * ADIM] = __float2half_rn(v);
        }
    }
    atomicAdd(&sum[n * SADIM + f], s);
    atomicAdd(&ssq[n * SADIM + f], s2);
}

__global__ void k_finalize(const float* __restrict__ sum, const float* __restrict__ ssq,
                           float* __restrict__ mean, float* __restrict__ istd) {
    int i = blockIdx.x * blockDim.x + threadIdx.x;
    if (i >= NAG * SADIM) return;
    float m = sum[i] * (1.f / BATCH);
    float v = ssq[i] * (1.f / BATCH) - m * m;
    mean[i] = m;
    istd[i] = rsqrtf(v + 1e-5f);
}

// WcombT[n][j][i] (j=out col 0..511, i=k 0..575), BN-folded, half
__global__ void k_prep_wcombT(const float* __restrict__ Wenc, const float* __restrict__ Ws,
                              const float* __restrict__ istd, __half* __restrict__ WT) {
    size_t idx = (size_t)blockIdx.x * blockDim.x + threadIdx.x;
    if (idx >= (size_t)NAG * 512 * SADIM) return;
    int i = (int)(idx % SADIM);
    int j = (int)((idx / SADIM) % 512);
    int n = (int)(idx / (512 * SADIM));
    float is = istd[n * SADIM + i];
    float v;
    if (j < HDIM) v = Wenc[((size_t)n * SADIM + i) * HDIM + j] * is;
    else          v = (i < SDIM) ? Ws[((size_t)n * SDIM + i) * HDIM + (j - HDIM)] * is : 0.f;
    WT[idx] = __float2half_rn(v);
}

__global__ void k_biasfold(const float* __restrict__ benc, const float* __restrict__ bs,
                           const float* __restrict__ Wenc, const float* __restrict__ Ws,
                           const float* __restrict__ mean, const float* __restrict__ istd,
                           float* __restrict__ bcomb) {
    int idx = blockIdx.x * blockDim.x + threadIdx.x;
    if (idx >= NAG * 512) return;
    int n = idx / 512, j = idx % 512;
    float acc;
    if (j < HDIM) {
        acc = benc[n * HDIM + j];
        for (int i = 0; i < SADIM; ++i)
            acc -= mean[n * SADIM + i] * istd[n * SADIM + i] *
                   Wenc[((size_t)n * SADIM + i) * HDIM + j];
    } else {
        int jj = j - HDIM;
        acc = bs[n * HDIM + jj];
        for (int i = 0; i < SDIM; ++i)
            acc -= mean[n * SADIM + i] * istd[n * SADIM + i] *
                   Ws[((size_t)n * SDIM + i) * HDIM + jj];
    }
    bcomb[idx] = acc;
}

// WkvT[j][h] (512 x 256): j<256 -> Wk, else Wv. WselT[j][h] (256 x 256), contiguous after.
__global__ void k_prep_projT(const float* __restrict__ Wk, const float* __restrict__ Wv,
                             const float* __restrict__ Wsel,
                             __half* __restrict__ WkvT, __half* __restrict__ WselT) {
    int idx = blockIdx.x * blockDim.x + threadIdx.x;
    if (idx < 512 * 256) {
        int j = idx / 256, h = idx % 256;
        int jj = (j < 256) ? j : j - 256;
        int e = jj >> 4, d = jj & 15;
        const float* src = (j < 256) ? Wk : Wv;
        WkvT[idx] = __float2half_rn(src[((size_t)e * HDIM + h) * 16 + d]);
    } else if (idx < 512 * 256 + 256 * 256) {
        int t = idx - 512 * 256;
        int j = t / 256, h = t % 256;
        int e = j >> 4, d = j & 15;
        WselT[t] = __float2half_rn(Wsel[((size_t)e * HDIM + h) * 16 + d]);
    }
}

// Wc1pT[n][j][k] = Wc1[n][sk][j], sk = k<256 ? k+256 : k-256
__global__ void k_prep_wc1pT(const float* __restrict__ Wc1, __half* __restrict__ WT) {
    size_t idx = (size_t)blockIdx.x * blockDim.x + threadIdx.x;
    if (idx >= (size_t)NAG * 256 * 512) return;
    int k = (int)(idx % 512);
    int j = (int)((idx / 512) % 256);
    int n = (int)(idx / (512 * 256));
    int sk = (k < 256) ? (k + 256) : (k - 256);
    WT[idx] = __float2half_rn(Wc1[((size_t)n * 512 + sk) * 256 + j]);
}

// ---------------------------------------------------------------------------
// fp16 mma.sync GEMM, 4-stage cp.async pipeline, ldmatrix fragment loads.
// 128x128 block tile, 256 threads (8 warps = 2M x 4N), warp tile 64x32,
// K staged 32 halves. Smem rows pitch 40 halves (80B): every 8-row LDSM
// phase covers all 32 banks exactly once.
// bx >= bx_hi uses aoff_hi for A columns (merged kv+sel launch).
// Cols in [sc0, sc1) get bias + leaky-relu. Output half (Ch) or float (Cf).
// ---------------------------------------------------------------------------
#define NSTAGE 4
#define HPITCH 40
#define STAGEH (128 * HPITCH)            // halves per tile-stage
#define STAGEB (STAGEH * 2)              // 10240 bytes
#define GSMEM_BYTES (2 * NSTAGE * STAGEB) // 81920

__global__ void __launch_bounds__(256)
k_gemm_h(const __half* __restrict__ A, int lda, int aoff,
         const __half* __restrict__ A2, int lda2, int ksplit,
         int bx_hi, int aoff_hi,
         const __half* __restrict__ WT, size_t w_astride, int ldwt,
         const float* __restrict__ bias, int bias_astride, int sc0, int sc1,
         __half* __restrict__ Ch, float* __restrict__ Cf,
         int ldc, int coff, int K)
{
    extern __shared__ __half smh[];
    __half* Ash = smh;
    __half* Bsh = smh + NSTAGE * STAGEH;
    const uint32_t sA = smem_u32(Ash);
    const uint32_t sB = smem_u32(Bsh);

    const int tid  = threadIdx.x;
    const int lane = tid & 31;
    const int wid  = tid >> 5;
    const int warpM = wid & 1;
    const int warpN = wid >> 1;
    const int lq = lane >> 2;
    const int lr = lane & 3;

    const int bx = blockIdx.x;
    const int n0 = bx * 128;
    const int r0 = blockIdx.y * 128;
    const int agent = r0 >> 15;
    const int aoff_eff = (bx >= bx_hi) ? aoff_hi : aoff;
    const __half* Wg = WT + (size_t)agent * w_astride + (size_t)n0 * ldwt;

    const int crow = tid >> 1;          // 0..127
    const int ckq  = (tid & 1) * 2;     // 16B-chunk base {0,2} of 4 per row

    // ldmatrix per-lane fragment address offsets (bytes within a stage tile)
    const uint32_t aFragOff =
        (uint32_t)(((warpM * 64 + (lane & 15)) * HPITCH + (lane >> 4) * 8) * 2);
    const uint32_t bFragOff =
        (uint32_t)(((warpN * 32 + (lane & 7)) * HPITCH + ((lane >> 3) & 1) * 8) * 2);

    float acc[4][4][4];
    #pragma unroll
    for (int mt = 0; mt < 4; ++mt)
        #pragma unroll
        for (int nt = 0; nt < 4; ++nt)
            #pragma unroll
            for (int i = 0; i < 4; ++i) acc[mt][nt][i] = 0.f;

    const int nk = K >> 5;

    auto issue = [&](int s) {
        int buf = s & (NSTAGE - 1);
        int kb = s << 5;
        const __half* asrc;
        if (kb < ksplit) asrc = A  + (size_t)(r0 + crow) * lda  + aoff_eff + kb;
        else             asrc = A2 + (size_t)(r0 + crow) * lda2 + (kb - ksplit);
        uint32_t ab = sA + (uint32_t)(buf * STAGEB + crow * (HPITCH * 2));
        cp_async16(ab + ckq * 16,       asrc + ckq * 8);
        cp_async16(ab + (ckq + 1) * 16, asrc + (ckq + 1) * 8);
        const __half* bsrc = Wg + (size_t)crow * ldwt + kb;
        uint32_t bb = sB + (uint32_t)(buf * STAGEB + crow * (HPITCH * 2));
        cp_async16(bb + ckq * 16,       bsrc + ckq * 8);
        cp_async16(bb + (ckq + 1) * 16, bsrc + (ckq + 1) * 8);
        cp_commit();
    };

    #pragma unroll
    for (int s = 0; s < NSTAGE - 1; ++s) issue(s);   // nk >= 8 always

    for (int i = 0; i < nk; ++i) {
        cp_wait<NSTAGE - 2>();
        __syncthreads();
        if (i + NSTAGE - 1 < nk) issue(i + NSTAGE - 1);

        int buf = i & (NSTAGE - 1);
        uint32_t aTile = sA + buf * STAGEB + aFragOff;
        uint32_t bTile = sB + buf * STAGEB + bFragOff;
        #pragma unroll
        for (int k0 = 0; k0 < 32; k0 += 16) {
            unsigned af[4][4], bf[4][2];
            #pragma unroll
            for (int mt = 0; mt < 4; ++mt)
                ldsm_x4(af[mt], aTile + k0 * 2 + mt * (16 * HPITCH * 2));
            #pragma unroll
            for (int nt = 0; nt < 4; ++nt)
                ldsm_x2(bf[nt], bTile + k0 * 2 + nt * (8 * HPITCH * 2));
            #pragma unroll
            for (int mt = 0; mt < 4; ++mt)
                #pragma unroll
                for (int nt = 0; nt < 4; ++nt)
                    mma_f16(acc[mt][nt], af[mt], bf[nt]);
        }
    }

    // epilogue: bias + leaky-relu on cols in [sc0, sc1); half or float store
    #pragma unroll
    for (int mt = 0; mt < 4; ++mt) {
        int r = r0 + warpM * 64 + mt * 16 + lq;
        #pragma unroll
        for (int nt = 0; nt < 4; ++nt) {
            int gc = bx * 128 + warpN * 32 + nt * 8 + 2 * lr;
            float v0 = acc[mt][nt][0], v1 = acc[mt][nt][1];
            float v2 = acc[mt][nt][2], v3 = acc[mt][nt][3];
            if (gc >= sc0 && gc < sc1) {
                float b0 = bias[(size_t)agent * bias_astride + (gc     - sc0)];
                float b1 = bias[(size_t)agent * bias_astride + (gc + 1 - sc0)];
                v0 += b0; v1 += b1; v2 += b0; v3 += b1;
                v0 = v0 > 0.f ? v0 : 0.01f * v0;
                v1 = v1 > 0.f ? v1 : 0.01f * v1;
                v2 = v2 > 0.f ? v2 : 0.01f * v2;
                v3 = v3 > 0.f ? v3 : 0.01f * v3;
            }
            if (Ch) {
                *(uint32_t*)(Ch + (size_t)r * ldc + coff + gc) =
                    h2bits(__floats2half2_rn(v0, v1));
                *(uint32_t*)(Ch + (size_t)(r + 8) * ldc + coff + gc) =
                    h2bits(__floats2half2_rn(v2, v3));
            } else {
                *(float2*)(Cf + (size_t)r * ldc + coff + gc)       = make_float2(v0, v1);
                *(float2*)(Cf + (size_t)(r + 8) * ldc + coff + gc) = make_float2(v2, v3);
            }
        }
    }
}

// ---------------------------------------------------------------------------
// Attention: half in (KVS), half out (`other` into ENC cols 0..255)
// ---------------------------------------------------------------------------
__global__ void __launch_bounds__(256)
k_attn(const __half* __restrict__ kvs, __half* __restrict__ enc) {
    __shared__ float sh[4][4][768];    // 48KB
    int tid = threadIdx.x;
    int b0 = blockIdx.x * 4;
    for (int t = tid; t < 1536; t += 256) {
        int row = t / 96, c8 = t % 96;
        int bl = row >> 2, ag = row & 3;
        uint4 v = *(const uint4*)(kvs + ((size_t)ag * BATCH + b0 + bl) * 768 + c8 * 8);
        const __half2* hp = (const __half2*)&v;
        float* dst = &sh[bl][ag][c8 * 8];
        #pragma unroll
        for (int j = 0; j < 4; ++j) {
            float2 f = __half22float2(hp[j]);
            dst[2 * j] = f.x; dst[2 * j + 1] = f.y;
        }
    }
    __syncthreads();

    int bl = tid >> 6, rem = tid & 63, e = rem >> 2, i = rem & 3;
    const float* selp = &sh[bl][i][512 + e * 16];
    float logits[4];
    #pragma unroll
    for (int j = 0; j < 4; ++j) {
        const float* kp = &sh[bl][j][e * 16];
        float acc = 0.f;
        #pragma unroll
        for (int d = 0; d < 16; ++d) acc += selp[d] * kp[d];
        logits[j] = acc * 0.25f;
    }
    logits[i] = -1e9f;
    float mx = fmaxf(fmaxf(logits[0], logits[1]), fmaxf(logits[2], logits[3]));
    float p[4], s = 0.f;
    #pragma unroll
    for (int j = 0; j < 4; ++j) { p[j] = __expf(logits[j] - mx); s += p[j]; }
    float inv = 1.f / s;
    float out[16];
    #pragma unroll
    for (int d = 0; d < 16; ++d) out[d] = 0.f;
    #pragma unroll
    for (int j = 0; j < 4; ++j) {
        float pj = p[j] * inv;
        const float* vp = &sh[bl][j][256 + e * 16];
        #pragma unroll
        for (int d = 0; d < 16; ++d) out[d] += pj * vp[d];
    }
    __half* dst = enc + ((size_t)i * BATCH + b0 + bl) * 512 + e * 16;
    uint4 o;
    o.x = h2bits(__floats2half2_rn(out[0], out[1]));
    o.y = h2bits(__floats2half2_rn(out[2], out[3]));
    o.z = h2bits(__floats2half2_rn(out[4], out[5]));
    o.w = h2bits(__floats2half2_rn(out[6], out[7]));
    *(uint4*)dst = o;
    o.x = h2bits(__floats2half2_rn(out[8], out[9]));
    o.y = h2bits(__floats2half2_rn(out[10], out[11]));
    o.z = h2bits(__floats2half2_rn(out[12], out[13]));
    o.w = h2bits(__floats2half2_rn(out[14], out[15]));
    *(uint4*)(dst + 8) = o;
}

// ---------------------------------------------------------------------------
__global__ void __launch_bounds__(256)
k_fc2(const float* __restrict__ actions, const float* __restrict__ Wc2,
      const float* __restrict__ bc2, const __half* __restrict__ H,
      float* __restrict__ out) {
    int row = blockIdx.x * 8 + (threadIdx.x >> 5);
    int lane = threadIdx.x & 31;
    int n = row >> 15;
    const float* arow = actions + (size_t)row * ADIM;
    float bestv = -1e30f; int besti = ADIM;
    for (int c = lane; c < ADIM; c += 32) {
        float v = arow[c];
        if (v > bestv || (v == bestv && c < besti)) { bestv = v; besti = c; }
    }
    #pragma unroll
    for (int off = 16; off; off >>= 1) {
        float ov = __shfl_down_sync(0xffffffffu, bestv, off);
        int   oi = __shfl_down_sync(0xffffffffu, besti, off);
        if (ov > bestv || (ov == bestv && oi < besti)) { bestv = ov; besti = oi; }
    }
    besti = __shfl_sync(0xffffffffu, besti, 0);

    const __half* hrow = H + (size_t)row * HDIM;
    const float* wcol = Wc2 + (size_t)n * HDIM * ADIM + besti;
    float acc = 0.f;
    #pragma unroll 4
    for (int k = lane; k < HDIM; k += 32)
        acc += __half2float(hrow[k]) * wcol[(size_t)k * ADIM];
    #pragma unroll
    for (int off = 16; off; off >>= 1)
        acc += __shfl_down_sync(0xffffffffu, acc, off);
    if (lane == 0) out[row] = acc + bc2[n * ADIM + besti];
}

// ---------------------------------------------------------------------------
extern "C" void kernel_launch(void* const* d_in, const int* in_sizes, int n_in,
                              void* d_out, int out_size) {
    (void)in_sizes; (void)n_in; (void)out_size;
    const float* states  = (const float*)d_in[0];
    const float* actions = (const float*)d_in[1];
    const float* Wenc    = (const float*)d_in[2];
    const float* benc    = (const float*)d_in[3];
    const float* Ws      = (const float*)d_in[4];
    const float* bs      = (const float*)d_in[5];
    const float* Wk      = (const float*)d_in[6];
    const float* Wsel    = (const float*)d_in[7];
    const float* Wv      = (const float*)d_in[8];
    const float* bv      = (const float*)d_in[9];
    const float* Wc1     = (const float*)d_in[10];
    const float* bc1     = (const float*)d_in[11];
    const float* Wc2     = (const float*)d_in[12];
    const float* bc2     = (const float*)d_in[13];
    float* out = (float*)d_out;

    float* S = nullptr;
    cudaGetSymbolAddress((void**)&S, g_scratch);
    float* SUM    = S + O_SUM;
    float* SSQ    = S + O_SSQ;
    float* MEAN   = S + O_MEAN;
    float* ISTD   = S + O_ISTD;
    float* BCOMB  = S + O_BCOMB;
    __half* WCOMBTh = (__half*)(S + O_WCOMBT);
    __half* WKVTh   = (__half*)(S + O_WKVT);   // WSELT contiguous after -> [768][256]
    __half* WSELTh  = (__half*)(S + O_WSELT);
    __half* WC1PTh  = (__half*)(S + O_WC1PT);
    __half* ENCh    = (__half*)(S + O_ENC);
    __half* KVSh    = (__half*)(S + O_KVS);
    __half* HBUFh   = (__half*)(S + O_H);
    __half* STH     = (__half*)(S + O_STH);
    __half* ATH     = (__half*)(S + O_ATH);

    const int BIG = 1 << 30;

    cudaFuncSetAttribute(k_gemm_h, cudaFuncAttributeMaxDynamicSharedMemorySize, GSMEM_BYTES);

    // 1) batch stats (fused half input copies)
    k_zero<<<(4608 + 255) / 256, 256>>>(SUM, 4608);
    k_stats<<<dim3(4, 64), 576>>>(states, actions, SUM, SSQ, STH, ATH);
    k_finalize<<<(2304 + 255) / 256, 256>>>(SUM, SSQ, MEAN, ISTD);

    // 2) weight prep (BN fold + transpose + half)
    k_prep_wcombT<<<(int)(((size_t)NAG * 512 * SADIM + 255) / 256), 256>>>(Wenc, Ws, ISTD, WCOMBTh);
    k_biasfold<<<(NAG * 512 + 255) / 256, 256>>>(benc, bs, Wenc, Ws, MEAN, ISTD, BCOMB);
    k_prep_projT<<<(512 * 256 + 256 * 256 + 255) / 256, 256>>>(Wk, Wv, Wsel, WKVTh, WSELTh);
    k_prep_wc1pT<<<(int)(((size_t)NAG * 256 * 512 + 255) / 256), 256>>>(Wc1, WC1PTh);

    // 3) encoder GEMM: [STH|ATH] (K=576) -> ENC [sa_enc|s_enc] (half)
    k_gemm_h<<<dim3(4, ROWS / 128), 256, GSMEM_BYTES>>>(
        STH, SDIM, 0, ATH, ADIM, SDIM,
        BIG, 0,
        WCOMBTh, (size_t)512 * SADIM, SADIM,
        BCOMB, 512, 0, BIG,
        ENCh, nullptr, 512, 0, SADIM);
    // 4) keys|vals|sel merged: bx 0..3 read sa_enc, bx 4..5 read s_enc;
    //    weights = [WkvT; WselT] contiguous (768 x 256); vals (cols 256..511)
    //    get bv + lrelu.
    k_gemm_h<<<dim3(6, ROWS / 128), 256, GSMEM_BYTES>>>(
        ENCh, 512, 0, ENCh, 512, BIG,
        4, 256,
        WKVTh, 0, 256,
        bv, 0, 256, 512,
        KVSh, nullptr, 768, 0, 256);
    // 5) attention -> other (half) into ENC cols 0..255
    k_attn<<<BATCH / 4, 256>>>(KVSh, ENCh);
    // 6) critic fc1: ENC (K=512) @ Wc1pT -> H (bc1 + lrelu, half out)
    k_gemm_h<<<dim3(2, ROWS / 128), 256, GSMEM_BYTES>>>(
        ENCh, 512, 0, ENCh, 512, BIG,
        BIG, 0,
        WC1PTh, (size_t)256 * 512, 512,
        bc1, 256, 0, BIG,
        HBUFh, nullptr, 256, 0, 512);
    // 7) fc2 + argmax gather
    k_fc2<<<ROWS / 8, 256>>>(actions, Wc2, bc2, HBUFh, out);
}